// round 5
// baseline (speedup 1.0000x reference)
#include <cuda_runtime.h>
#include <math.h>

// ---------------- problem constants ----------------
#define BATCH   16
#define TOPN    4
#define NA      1614
#define OUT_S   224
#define IM_S    448
#define PAD_S   224
#define HP_S    896

#define NPART   (BATCH*TOPN*3*OUT_S*OUT_S)   // 9,633,792
#define OFF_TIDX  NPART
#define OFF_TPROB (NPART + BATCH*TOPN)
#define OFF_SCORE (NPART + 2*BATCH*TOPN)

// conv1 tiling
#define KSPLIT  16
#define ICPS    (2048/KSPLIT)    // 128 input channels per split
#define ICSTEP  8
#define NP1     (BATCH*128*196)  // 401,408

// ---------------- scratch (static device memory, no allocs) ----------------
__device__ float g_part1[(size_t)KSPLIT * NP1];   // ~25.7 MB
__device__ float g_d1[NP1];                       // post-relu d1  [B,128,14,14]
__device__ float g_d2[BATCH*128*49];              // post-relu d2  [B,128,7,7]
__device__ float g_d3[BATCH*128*16];              // post-relu d3  [B,128,4,4]
__device__ float g_score[BATCH*NA];               // rpn scores
__device__ int   g_topidx[BATCH*TOPN];

__device__ __forceinline__ float neg_inf() { return __int_as_float(0xff800000); }

// ================= conv1: 2048->128, 3x3, pad 1, on 14x14 =================
// grid (KSPLIT, 2 oc-tiles of 64, BATCH), block 224 = 28 pos-groups x 8 oc-groups
// thread tile: 7 positions x 8 oc. Split-K partials written to g_part1 (full
// coverage, no zero-init needed), reduced deterministically in finalize1.
__global__ void __launch_bounds__(224) conv1_kernel(const float* __restrict__ in,
                                                    const float* __restrict__ w)
{
    const int ks  = blockIdx.x;
    const int oct = blockIdx.y;
    const int b   = blockIdx.z;
    const int tid = threadIdx.x;
    const int pg  = tid % 28;      // position group: positions pg*7 .. pg*7+6
    const int ocg = tid / 28;      // oc group: oc = oct*64 + ocg*8 .. +7

    __shared__ float in_s[ICSTEP][256];        // 16x16 zero-padded planes
    __shared__ float w_s[ICSTEP * 9][64];      // [ic*9+tap][oc]

    float acc[7][8];
#pragma unroll
    for (int i = 0; i < 7; i++)
#pragma unroll
        for (int o = 0; o < 8; o++) acc[i][o] = 0.f;

    int base[7];
#pragma unroll
    for (int i = 0; i < 7; i++) {
        int p = pg * 7 + i;
        base[i] = (p / 14 + 1) * 16 + (p % 14) + 1;   // into padded 16x16
    }

    const float* inb = in + (size_t)b * 2048 * 196;
    const float* wb  = w  + (size_t)(oct * 64) * 18432;   // 18432 = 2048*9
    const int icb0 = ks * ICPS;

    for (int ch = 0; ch < ICPS / ICSTEP; ch++) {
        const int icb = icb0 + ch * ICSTEP;

        // ---- load ICSTEP padded input planes ----
        for (int idx = tid; idx < ICSTEP * 256; idx += 224) {
            int ic = idx >> 8, s = idx & 255, sy = s >> 4, sx = s & 15;
            float v = 0.f;
            if (sy >= 1 && sy <= 14 && sx >= 1 && sx <= 14)
                v = __ldg(&inb[(size_t)(icb + ic) * 196 + (sy - 1) * 14 + (sx - 1)]);
            in_s[ic][s] = v;
        }
        // ---- load weights: ICSTEP*9*64 = 4608 floats ----
        for (int idx = tid; idx < ICSTEP * 9 * 64; idx += 224) {
            int oc = idx / 72, r = idx % 72, ic = r / 9, t = r % 9;
            w_s[ic * 9 + t][oc] =
                __ldg(&wb[(size_t)oc * 18432 + (size_t)(icb + ic) * 9 + t]);
        }
        __syncthreads();

#pragma unroll
        for (int ic = 0; ic < ICSTEP; ic++) {
#pragma unroll
            for (int t = 0; t < 9; t++) {
                const int off = (t / 3 - 1) * 16 + (t % 3 - 1);
                const float4 w0 = *(const float4*)&w_s[ic * 9 + t][ocg * 8];
                const float4 w1 = *(const float4*)&w_s[ic * 9 + t][ocg * 8 + 4];
#pragma unroll
                for (int i = 0; i < 7; i++) {
                    float v = in_s[ic][base[i] + off];
                    acc[i][0] = fmaf(v, w0.x, acc[i][0]);
                    acc[i][1] = fmaf(v, w0.y, acc[i][1]);
                    acc[i][2] = fmaf(v, w0.z, acc[i][2]);
                    acc[i][3] = fmaf(v, w0.w, acc[i][3]);
                    acc[i][4] = fmaf(v, w1.x, acc[i][4]);
                    acc[i][5] = fmaf(v, w1.y, acc[i][5]);
                    acc[i][6] = fmaf(v, w1.z, acc[i][6]);
                    acc[i][7] = fmaf(v, w1.w, acc[i][7]);
                }
            }
        }
        __syncthreads();
    }

    float* pp = g_part1 + (size_t)ks * NP1 +
                ((size_t)b * 128 + oct * 64 + ocg * 8) * 196 + pg * 7;
#pragma unroll
    for (int o = 0; o < 8; o++)
#pragma unroll
        for (int i = 0; i < 7; i++)
            pp[(size_t)o * 196 + i] = acc[i][o];
}

// deterministic split-K reduce + bias + relu
__global__ void finalize1_kernel(const float* __restrict__ bias)
{
    int n = blockIdx.x * 256 + threadIdx.x;
    if (n >= NP1) return;
    float s = 0.f;
#pragma unroll
    for (int k = 0; k < KSPLIT; k++) s += g_part1[(size_t)k * NP1 + n];
    int oc = (n / 196) & 127;
    g_d1[n] = fmaxf(s + __ldg(&bias[oc]), 0.f);
}

// ================= conv2: 128->128, 3x3, stride 2, pad 1 (14->7) =========
__global__ void conv2_kernel(const float* __restrict__ w, const float* __restrict__ bias)
{
    int n = blockIdx.x * 256 + threadIdx.x;
    if (n >= BATCH * 128 * 49) return;
    int p = n % 49, oc = (n / 49) & 127, b = n / (49 * 128);
    int oy = p / 7, ox = p % 7;
    const float* ib = g_d1 + (size_t)b * 128 * 196;
    const float* wb = w + (size_t)oc * 128 * 9;
    float acc = __ldg(&bias[oc]);
#pragma unroll
    for (int ky = 0; ky < 3; ky++) {
        int iy = 2 * oy + ky - 1;
        if (iy < 0 || iy >= 14) continue;
#pragma unroll
        for (int kx = 0; kx < 3; kx++) {
            int ix = 2 * ox + kx - 1;
            if (ix < 0 || ix >= 14) continue;
            const float* ip = ib + iy * 14 + ix;
            const float* wp = wb + ky * 3 + kx;
            for (int ic = 0; ic < 128; ic++)
                acc = fmaf(ip[(size_t)ic * 196], __ldg(&wp[(size_t)ic * 9]), acc);
        }
    }
    g_d2[n] = fmaxf(acc, 0.f);
}

// ================= conv3: 128->128, 3x3, stride 2, pad 1 (7->4) ==========
__global__ void conv3_kernel(const float* __restrict__ w, const float* __restrict__ bias)
{
    int n = blockIdx.x * 256 + threadIdx.x;
    if (n >= BATCH * 128 * 16) return;
    int p = n % 16, oc = (n / 16) & 127, b = n / (16 * 128);
    int oy = p / 4, ox = p % 4;
    const float* ib = g_d2 + (size_t)b * 128 * 49;
    const float* wb = w + (size_t)oc * 128 * 9;
    float acc = __ldg(&bias[oc]);
#pragma unroll
    for (int ky = 0; ky < 3; ky++) {
        int iy = 2 * oy + ky - 1;
        if (iy < 0 || iy >= 7) continue;
#pragma unroll
        for (int kx = 0; kx < 3; kx++) {
            int ix = 2 * ox + kx - 1;
            if (ix < 0 || ix >= 7) continue;
            const float* ip = ib + iy * 7 + ix;
            const float* wp = wb + ky * 3 + kx;
            for (int ic = 0; ic < 128; ic++)
                acc = fmaf(ip[(size_t)ic * 49], __ldg(&wp[(size_t)ic * 9]), acc);
        }
    }
    g_d3[n] = fmaxf(acc, 0.f);
}

// ================= tidy 1x1 convs -> concatenated scores =================
// score[b, 0:1176]    = t1[b,c,p] at c*196+p   (from d1)
// score[b, 1176:1470] = t2[b,c,p] at c*49+p    (from d2)
// score[b, 1470:1614] = t3[b,c,p] at c*16+p    (from d3)
__global__ void tidy_kernel(const float* __restrict__ wt1, const float* __restrict__ bt1,
                            const float* __restrict__ wt2, const float* __restrict__ bt2,
                            const float* __restrict__ wt3, const float* __restrict__ bt3,
                            float* __restrict__ out)
{
    int n = blockIdx.x * 256 + threadIdx.x;
    if (n >= BATCH * NA) return;
    int b = n / NA, j = n % NA;
    const float* src; const float* wt; float bias; int c, p, stride;
    if (j < 1176) {
        c = j / 196; p = j % 196;
        src = g_d1 + (size_t)b * 128 * 196; stride = 196;
        wt = wt1; bias = __ldg(&bt1[c]);
    } else if (j < 1470) {
        int jj = j - 1176; c = jj / 49; p = jj % 49;
        src = g_d2 + (size_t)b * 128 * 49; stride = 49;
        wt = wt2; bias = __ldg(&bt2[c]);
    } else {
        int jj = j - 1470; c = jj / 16; p = jj % 16;
        src = g_d3 + (size_t)b * 128 * 16; stride = 16;
        wt = wt3; bias = __ldg(&bt3[c]);
    }
    float acc = bias;
    const float* wp = wt + (size_t)c * 128;
    for (int ic = 0; ic < 128; ic++)
        acc = fmaf(src[(size_t)ic * stride + p], __ldg(&wp[ic]), acc);
    g_score[n] = acc;
    out[OFF_SCORE + n] = acc;
}

// ================= greedy NMS, TOPN picks, suppress IoU >= 0.25 ==========
__global__ void nms_kernel(const int* __restrict__ anchors, float* __restrict__ out)
{
    int b = blockIdx.x, tid = threadIdx.x;   // 256 threads
    __shared__ float s[NA];
    __shared__ float rv[256];
    __shared__ int   ri[256];
    __shared__ float pbox[4];
    __shared__ float parea;

    for (int j = tid; j < NA; j += 256) s[j] = g_score[b * NA + j];
    __syncthreads();

    for (int k = 0; k < TOPN; k++) {
        float bv = neg_inf(); int bi = 0x7fffffff;
        for (int j = tid; j < NA; j += 256) {
            float v = s[j];
            if (v > bv || (v == bv && j < bi)) { bv = v; bi = j; }
        }
        rv[tid] = bv; ri[tid] = bi;
        __syncthreads();
        for (int st = 128; st > 0; st >>= 1) {
            if (tid < st) {
                float v2 = rv[tid + st]; int i2 = ri[tid + st];
                if (v2 > rv[tid] || (v2 == rv[tid] && i2 < ri[tid])) {
                    rv[tid] = v2; ri[tid] = i2;
                }
            }
            __syncthreads();
        }
        if (tid == 0) {
            int pick = ri[0];
            const int* a = anchors + (size_t)pick * 4;
            pbox[0] = (float)a[0]; pbox[1] = (float)a[1];
            pbox[2] = (float)a[2]; pbox[3] = (float)a[3];
            parea = (pbox[2] - pbox[0]) * (pbox[3] - pbox[1]);
            g_topidx[b * TOPN + k] = pick;
            out[OFF_TIDX  + b * TOPN + k] = (float)pick;
            out[OFF_TPROB + b * TOPN + k] = rv[0];
        }
        __syncthreads();
        float y0 = pbox[0], x0 = pbox[1], y1 = pbox[2], x1 = pbox[3], pa = parea;
        for (int j = tid; j < NA; j += 256) {
            const int* a = anchors + (size_t)j * 4;
            float ay0 = (float)a[0], ax0 = (float)a[1];
            float ay1 = (float)a[2], ax1 = (float)a[3];
            float iy = fmaxf(fminf(ay1, y1) - fmaxf(ay0, y0), 0.f);
            float ix = fmaxf(fminf(ax1, x1) - fmaxf(ax0, x0), 0.f);
            float inter = iy * ix;
            float area  = (ay1 - ay0) * (ax1 - ax0);
            float iou = inter / (area + pa - inter);
            if (iou >= 0.25f) s[j] = neg_inf();
        }
        __syncthreads();
    }
}

// ================= crop + bilinear resize (align_corners=True) ===========
__device__ __forceinline__ float fetchpix(const float* __restrict__ xb, int yy, int xx)
{
    yy -= PAD_S; xx -= PAD_S;
    if ((unsigned)yy < (unsigned)IM_S && (unsigned)xx < (unsigned)IM_S)
        return __ldg(&xb[(size_t)yy * IM_S + xx]);
    return 0.f;
}

__global__ void crop_kernel(const float* __restrict__ x,
                            const int* __restrict__ anchors,
                            float* __restrict__ out)
{
    const int crop = blockIdx.x;      // 0..63  (b*4 + t)
    const int oy   = blockIdx.y;      // 0..223
    const int ox   = threadIdx.x;     // 0..223
    const int b    = crop >> 2;

    const int pick = g_topidx[crop];
    const int* a = anchors + (size_t)pick * 4;
    float y0 = (float)a[0], x0 = (float)a[1], y1 = (float)a[2], x1 = (float)a[3];

    float ty = (float)oy / 223.0f;
    float tx = (float)ox / 223.0f;
    float ys = y0 + ty * (y1 - y0 - 1.0f);
    float xs = x0 + tx * (x1 - x0 - 1.0f);
    int yi0 = (int)floorf(ys); int yi1 = min(yi0 + 1, HP_S - 1);
    int xi0 = (int)floorf(xs); int xi1 = min(xi0 + 1, HP_S - 1);
    float wy = ys - (float)yi0;
    float wx = xs - (float)xi0;
    float c00 = (1.f - wy) * (1.f - wx);
    float c01 = (1.f - wy) * wx;
    float c10 = wy * (1.f - wx);
    float c11 = wy * wx;

#pragma unroll
    for (int c = 0; c < 3; c++) {
        const float* xb = x + ((size_t)b * 3 + c) * IM_S * IM_S;
        float v = fetchpix(xb, yi0, xi0) * c00
                + fetchpix(xb, yi0, xi1) * c01
                + fetchpix(xb, yi1, xi0) * c10
                + fetchpix(xb, yi1, xi1) * c11;
        out[(((size_t)crop * 3 + c) * OUT_S + oy) * OUT_S + ox] = v;
    }
}

// =========================================================================
extern "C" void kernel_launch(void* const* d_in, const int* in_sizes, int n_in,
                              void* d_out, int out_size)
{
    const float* x    = (const float*)d_in[0];
    const float* rpn  = (const float*)d_in[1];
    const float* w1   = (const float*)d_in[2];
    const float* b1   = (const float*)d_in[3];
    const float* w2   = (const float*)d_in[4];
    const float* b2   = (const float*)d_in[5];
    const float* w3   = (const float*)d_in[6];
    const float* b3   = (const float*)d_in[7];
    const float* wt1  = (const float*)d_in[8];
    const float* bt1  = (const float*)d_in[9];
    const float* wt2  = (const float*)d_in[10];
    const float* bt2  = (const float*)d_in[11];
    const float* wt3  = (const float*)d_in[12];
    const float* bt3  = (const float*)d_in[13];
    const int*   anc  = (const int*)d_in[14];
    float* out = (float*)d_out;

    conv1_kernel<<<dim3(KSPLIT, 2, BATCH), 224>>>(rpn, w1);
    finalize1_kernel<<<(NP1 + 255) / 256, 256>>>(b1);
    conv2_kernel<<<(BATCH * 128 * 49 + 255) / 256, 256>>>(w2, b2);
    conv3_kernel<<<(BATCH * 128 * 16 + 255) / 256, 256>>>(w3, b3);
    tidy_kernel<<<(BATCH * NA + 255) / 256, 256>>>(wt1, bt1, wt2, bt2, wt3, bt3, out);
    nms_kernel<<<BATCH, 256>>>(anc, out);
    crop_kernel<<<dim3(BATCH * TOPN, OUT_S), OUT_S>>>(x, anc, out);
}

// round 6
// speedup vs baseline: 1.0930x; 1.0930x over previous
#include <cuda_runtime.h>
#include <math.h>

// ---------------- problem constants ----------------
#define BATCH   16
#define TOPN    4
#define NA      1614
#define OUT_S   224
#define IM_S    448
#define PAD_S   224
#define HP_S    896

#define NPART   (BATCH*TOPN*3*OUT_S*OUT_S)   // 9,633,792
#define OFF_TIDX  NPART
#define OFF_TPROB (NPART + BATCH*TOPN)
#define OFF_SCORE (NPART + 2*BATCH*TOPN)

// conv1 tiling
#define KSPLIT  32
#define ICPS    (2048/KSPLIT)    // 64 input channels per split
#define ICSTEP  8
#define NP1     (BATCH*128*196)  // 401,408

// conv2/conv3 split-K
#define KS2     4                // 32 ic per split
#define KS3     8                // 16 ic per split
#define N2      (BATCH*128*49)   // 100,352
#define N3      (BATCH*128*16)   // 32,768

// ---------------- scratch (static device memory, no allocs) ----------------
__device__ float g_part1[(size_t)KSPLIT * NP1];   // ~51.4 MB
__device__ float g_d1[NP1];                       // post-relu d1  [B,128,14,14]
__device__ float g_p2[(size_t)KS2 * N2];
__device__ float g_d2[N2];                        // post-relu d2  [B,128,7,7]
__device__ float g_p3[(size_t)KS3 * N3];
__device__ float g_d3[N3];                        // post-relu d3  [B,128,4,4]
__device__ float g_score[BATCH*NA];               // rpn scores
__device__ int   g_topidx[BATCH*TOPN];

__device__ __forceinline__ float neg_inf() { return __int_as_float(0xff800000); }

// ---------------- packed f32x2 helpers ----------------
typedef unsigned long long u64;

__device__ __forceinline__ u64 pk2(float lo, float hi) {
    u64 r;
    asm("mov.b64 %0, {%1, %2};" : "=l"(r) : "f"(lo), "f"(hi));
    return r;
}
__device__ __forceinline__ void fma2(u64& d, u64 a, u64 b) {
    asm("fma.rn.f32x2 %0, %1, %2, %0;" : "+l"(d) : "l"(a), "l"(b));
}
__device__ __forceinline__ float2 upk2(u64 v) {
    float2 r;
    asm("mov.b64 {%0, %1}, %2;" : "=f"(r.x), "=f"(r.y) : "l"(v));
    return r;
}

// ================= conv1: 2048->128, 3x3, pad 1, on 14x14 =================
// grid (KSPLIT, 2 oc-tiles of 64, BATCH) = 1024 blocks, block 224 threads
// = 28 pos-groups x 8 oc-groups. Thread tile: 7 positions x 8 oc, accumulated
// as 4 packed f32x2 pairs (FFMA2 doubles fp32 lane throughput; pack movs go
// to the alu pipe and dual-issue against the fma pipe).
__global__ void __launch_bounds__(224) conv1_kernel(const float* __restrict__ in,
                                                    const float* __restrict__ w)
{
    const int ks  = blockIdx.x;
    const int oct = blockIdx.y;
    const int b   = blockIdx.z;
    const int tid = threadIdx.x;
    const int pg  = tid % 28;      // position group: positions pg*7 .. pg*7+6
    const int ocg = tid / 28;      // oc group: oc = oct*64 + ocg*8 .. +7

    __shared__ float in_s[ICSTEP][256];        // 16x16 zero-padded planes
    __shared__ float w_s[ICSTEP * 9][64];      // [ic*9+tap][oc]

    u64 acc[7][4];
#pragma unroll
    for (int i = 0; i < 7; i++)
#pragma unroll
        for (int o = 0; o < 4; o++) acc[i][o] = 0ULL;   // two packed +0.0f

    int base[7];
#pragma unroll
    for (int i = 0; i < 7; i++) {
        int p = pg * 7 + i;
        base[i] = (p / 14 + 1) * 16 + (p % 14) + 1;   // into padded 16x16
    }

    const float* inb = in + (size_t)b * 2048 * 196;
    const float* wb  = w  + (size_t)(oct * 64) * 18432;   // 18432 = 2048*9
    const int icb0 = ks * ICPS;

    for (int ch = 0; ch < ICPS / ICSTEP; ch++) {
        const int icb = icb0 + ch * ICSTEP;

        // ---- load ICSTEP padded input planes ----
        for (int idx = tid; idx < ICSTEP * 256; idx += 224) {
            int ic = idx >> 8, s = idx & 255, sy = s >> 4, sx = s & 15;
            float v = 0.f;
            if (sy >= 1 && sy <= 14 && sx >= 1 && sx <= 14)
                v = __ldg(&inb[(size_t)(icb + ic) * 196 + (sy - 1) * 14 + (sx - 1)]);
            in_s[ic][s] = v;
        }
        // ---- load weights: ICSTEP*9*64 = 4608 floats ----
        for (int idx = tid; idx < ICSTEP * 9 * 64; idx += 224) {
            int oc = idx / 72, r = idx % 72, ic = r / 9, t = r % 9;
            w_s[ic * 9 + t][oc] =
                __ldg(&wb[(size_t)oc * 18432 + (size_t)(icb + ic) * 9 + t]);
        }
        __syncthreads();

#pragma unroll
        for (int ic = 0; ic < ICSTEP; ic++) {
#pragma unroll
            for (int t = 0; t < 9; t++) {
                const int off = (t / 3 - 1) * 16 + (t % 3 - 1);
                const float4 w0 = *(const float4*)&w_s[ic * 9 + t][ocg * 8];
                const float4 w1 = *(const float4*)&w_s[ic * 9 + t][ocg * 8 + 4];
                const u64 wp0 = pk2(w0.x, w0.y);
                const u64 wp1 = pk2(w0.z, w0.w);
                const u64 wp2 = pk2(w1.x, w1.y);
                const u64 wp3 = pk2(w1.z, w1.w);
#pragma unroll
                for (int i = 0; i < 7; i++) {
                    float v = in_s[ic][base[i] + off];
                    u64 vv = pk2(v, v);
                    fma2(acc[i][0], vv, wp0);
                    fma2(acc[i][1], vv, wp1);
                    fma2(acc[i][2], vv, wp2);
                    fma2(acc[i][3], vv, wp3);
                }
            }
        }
        __syncthreads();
    }

    float* pp = g_part1 + (size_t)ks * NP1 +
                ((size_t)b * 128 + oct * 64 + ocg * 8) * 196 + pg * 7;
#pragma unroll
    for (int o = 0; o < 4; o++)
#pragma unroll
        for (int i = 0; i < 7; i++) {
            float2 f = upk2(acc[i][o]);
            pp[(size_t)(2 * o) * 196 + i]     = f.x;
            pp[(size_t)(2 * o + 1) * 196 + i] = f.y;
        }
}

// deterministic split-K reduce + bias + relu
__global__ void finalize1_kernel(const float* __restrict__ bias)
{
    int n = blockIdx.x * 256 + threadIdx.x;
    if (n >= NP1) return;
    float s = 0.f;
#pragma unroll
    for (int k = 0; k < KSPLIT; k++) s += g_part1[(size_t)k * NP1 + n];
    int oc = (n / 196) & 127;
    g_d1[n] = fmaxf(s + __ldg(&bias[oc]), 0.f);
}

// ================= conv2: 128->128, 3x3, stride 2, pad 1 (14->7) =========
// split-K over ic (KS2 splits of 32), 4 independent accumulators.
__global__ void conv2_kernel(const float* __restrict__ w)
{
    int n = blockIdx.x * 256 + threadIdx.x;
    if (n >= N2) return;
    const int ks = blockIdx.y;
    int p = n % 49, oc = (n / 49) & 127, b = n / (49 * 128);
    int oy = p / 7, ox = p % 7;
    const int icb = ks * 32;
    const float* ib = g_d1 + (size_t)b * 128 * 196 + (size_t)icb * 196;
    const float* wb = w + (size_t)oc * 1152 + (size_t)icb * 9;
    float a0 = 0.f, a1 = 0.f, a2 = 0.f, a3 = 0.f;
#pragma unroll
    for (int ky = 0; ky < 3; ky++) {
        int iy = 2 * oy + ky - 1;
        if (iy < 0 || iy >= 14) continue;
#pragma unroll
        for (int kx = 0; kx < 3; kx++) {
            int ix = 2 * ox + kx - 1;
            if (ix < 0 || ix >= 14) continue;
            const float* ip = ib + iy * 14 + ix;
            const float* wp = wb + ky * 3 + kx;
#pragma unroll 8
            for (int ic = 0; ic < 32; ic += 4) {
                a0 = fmaf(__ldg(&ip[(size_t)(ic + 0) * 196]), __ldg(&wp[(size_t)(ic + 0) * 9]), a0);
                a1 = fmaf(__ldg(&ip[(size_t)(ic + 1) * 196]), __ldg(&wp[(size_t)(ic + 1) * 9]), a1);
                a2 = fmaf(__ldg(&ip[(size_t)(ic + 2) * 196]), __ldg(&wp[(size_t)(ic + 2) * 9]), a2);
                a3 = fmaf(__ldg(&ip[(size_t)(ic + 3) * 196]), __ldg(&wp[(size_t)(ic + 3) * 9]), a3);
            }
        }
    }
    g_p2[(size_t)ks * N2 + n] = (a0 + a1) + (a2 + a3);
}

__global__ void reduce2_kernel(const float* __restrict__ bias)
{
    int n = blockIdx.x * 256 + threadIdx.x;
    if (n >= N2) return;
    float s = __ldg(&bias[(n / 49) & 127]);
#pragma unroll
    for (int k = 0; k < KS2; k++) s += g_p2[(size_t)k * N2 + n];
    g_d2[n] = fmaxf(s, 0.f);
}

// ================= conv3: 128->128, 3x3, stride 2, pad 1 (7->4) ==========
__global__ void conv3_kernel(const float* __restrict__ w)
{
    int n = blockIdx.x * 256 + threadIdx.x;
    if (n >= N3) return;
    const int ks = blockIdx.y;
    int p = n % 16, oc = (n / 16) & 127, b = n / (16 * 128);
    int oy = p / 4, ox = p % 4;
    const int icb = ks * 16;
    const float* ib = g_d2 + (size_t)b * 128 * 49 + (size_t)icb * 49;
    const float* wb = w + (size_t)oc * 1152 + (size_t)icb * 9;
    float a0 = 0.f, a1 = 0.f, a2 = 0.f, a3 = 0.f;
#pragma unroll
    for (int ky = 0; ky < 3; ky++) {
        int iy = 2 * oy + ky - 1;
        if (iy < 0 || iy >= 7) continue;
#pragma unroll
        for (int kx = 0; kx < 3; kx++) {
            int ix = 2 * ox + kx - 1;
            if (ix < 0 || ix >= 7) continue;
            const float* ip = ib + iy * 7 + ix;
            const float* wp = wb + ky * 3 + kx;
#pragma unroll 4
            for (int ic = 0; ic < 16; ic += 4) {
                a0 = fmaf(__ldg(&ip[(size_t)(ic + 0) * 49]), __ldg(&wp[(size_t)(ic + 0) * 9]), a0);
                a1 = fmaf(__ldg(&ip[(size_t)(ic + 1) * 49]), __ldg(&wp[(size_t)(ic + 1) * 9]), a1);
                a2 = fmaf(__ldg(&ip[(size_t)(ic + 2) * 49]), __ldg(&wp[(size_t)(ic + 2) * 9]), a2);
                a3 = fmaf(__ldg(&ip[(size_t)(ic + 3) * 49]), __ldg(&wp[(size_t)(ic + 3) * 9]), a3);
            }
        }
    }
    g_p3[(size_t)ks * N3 + n] = (a0 + a1) + (a2 + a3);
}

__global__ void reduce3_kernel(const float* __restrict__ bias)
{
    int n = blockIdx.x * 256 + threadIdx.x;
    if (n >= N3) return;
    float s = __ldg(&bias[(n / 16) & 127]);
#pragma unroll
    for (int k = 0; k < KS3; k++) s += g_p3[(size_t)k * N3 + n];
    g_d3[n] = fmaxf(s, 0.f);
}

// ================= tidy 1x1 convs -> concatenated scores =================
__global__ void tidy_kernel(const float* __restrict__ wt1, const float* __restrict__ bt1,
                            const float* __restrict__ wt2, const float* __restrict__ bt2,
                            const float* __restrict__ wt3, const float* __restrict__ bt3,
                            float* __restrict__ out)
{
    int n = blockIdx.x * 256 + threadIdx.x;
    if (n >= BATCH * NA) return;
    int b = n / NA, j = n % NA;
    const float* src; const float* wt; float bias; int c, p, stride;
    if (j < 1176) {
        c = j / 196; p = j % 196;
        src = g_d1 + (size_t)b * 128 * 196; stride = 196;
        wt = wt1; bias = __ldg(&bt1[c]);
    } else if (j < 1470) {
        int jj = j - 1176; c = jj / 49; p = jj % 49;
        src = g_d2 + (size_t)b * 128 * 49; stride = 49;
        wt = wt2; bias = __ldg(&bt2[c]);
    } else {
        int jj = j - 1470; c = jj / 16; p = jj % 16;
        src = g_d3 + (size_t)b * 128 * 16; stride = 16;
        wt = wt3; bias = __ldg(&bt3[c]);
    }
    const float4* wv = (const float4*)(wt + (size_t)c * 128);
    float a0 = 0.f, a1 = 0.f, a2 = 0.f, a3 = 0.f;
#pragma unroll 8
    for (int i = 0; i < 32; i++) {
        float4 w4 = __ldg(&wv[i]);
        int ic = 4 * i;
        a0 = fmaf(src[(size_t)(ic + 0) * stride + p], w4.x, a0);
        a1 = fmaf(src[(size_t)(ic + 1) * stride + p], w4.y, a1);
        a2 = fmaf(src[(size_t)(ic + 2) * stride + p], w4.z, a2);
        a3 = fmaf(src[(size_t)(ic + 3) * stride + p], w4.w, a3);
    }
    float acc = bias + ((a0 + a1) + (a2 + a3));
    g_score[n] = acc;
    out[OFF_SCORE + n] = acc;
}

// ================= greedy NMS, TOPN picks, suppress IoU >= 0.25 ==========
__global__ void nms_kernel(const int* __restrict__ anchors, float* __restrict__ out)
{
    int b = blockIdx.x, tid = threadIdx.x;   // 256 threads
    __shared__ float s[NA];
    __shared__ float rv[256];
    __shared__ int   ri[256];
    __shared__ float pbox[4];
    __shared__ float parea;

    for (int j = tid; j < NA; j += 256) s[j] = g_score[b * NA + j];
    __syncthreads();

    for (int k = 0; k < TOPN; k++) {
        float bv = neg_inf(); int bi = 0x7fffffff;
        for (int j = tid; j < NA; j += 256) {
            float v = s[j];
            if (v > bv || (v == bv && j < bi)) { bv = v; bi = j; }
        }
        rv[tid] = bv; ri[tid] = bi;
        __syncthreads();
        for (int st = 128; st > 0; st >>= 1) {
            if (tid < st) {
                float v2 = rv[tid + st]; int i2 = ri[tid + st];
                if (v2 > rv[tid] || (v2 == rv[tid] && i2 < ri[tid])) {
                    rv[tid] = v2; ri[tid] = i2;
                }
            }
            __syncthreads();
        }
        if (tid == 0) {
            int pick = ri[0];
            const int* a = anchors + (size_t)pick * 4;
            pbox[0] = (float)a[0]; pbox[1] = (float)a[1];
            pbox[2] = (float)a[2]; pbox[3] = (float)a[3];
            parea = (pbox[2] - pbox[0]) * (pbox[3] - pbox[1]);
            g_topidx[b * TOPN + k] = pick;
            out[OFF_TIDX  + b * TOPN + k] = (float)pick;
            out[OFF_TPROB + b * TOPN + k] = rv[0];
        }
        __syncthreads();
        float y0 = pbox[0], x0 = pbox[1], y1 = pbox[2], x1 = pbox[3], pa = parea;
        for (int j = tid; j < NA; j += 256) {
            const int* a = anchors + (size_t)j * 4;
            float ay0 = (float)a[0], ax0 = (float)a[1];
            float ay1 = (float)a[2], ax1 = (float)a[3];
            float iy = fmaxf(fminf(ay1, y1) - fmaxf(ay0, y0), 0.f);
            float ix = fmaxf(fminf(ax1, x1) - fmaxf(ax0, x0), 0.f);
            float inter = iy * ix;
            float area  = (ay1 - ay0) * (ax1 - ax0);
            float iou = inter / (area + pa - inter);
            if (iou >= 0.25f) s[j] = neg_inf();
        }
        __syncthreads();
    }
}

// ================= crop + bilinear resize (align_corners=True) ===========
__device__ __forceinline__ float fetchpix(const float* __restrict__ xb, int yy, int xx)
{
    yy -= PAD_S; xx -= PAD_S;
    if ((unsigned)yy < (unsigned)IM_S && (unsigned)xx < (unsigned)IM_S)
        return __ldg(&xb[(size_t)yy * IM_S + xx]);
    return 0.f;
}

__global__ void crop_kernel(const float* __restrict__ x,
                            const int* __restrict__ anchors,
                            float* __restrict__ out)
{
    const int crop = blockIdx.x;      // 0..63  (b*4 + t)
    const int oy   = blockIdx.y;      // 0..223
    const int ox   = threadIdx.x;     // 0..223
    const int b    = crop >> 2;

    const int pick = g_topidx[crop];
    const int* a = anchors + (size_t)pick * 4;
    float y0 = (float)a[0], x0 = (float)a[1], y1 = (float)a[2], x1 = (float)a[3];

    float ty = (float)oy / 223.0f;
    float tx = (float)ox / 223.0f;
    float ys = y0 + ty * (y1 - y0 - 1.0f);
    float xs = x0 + tx * (x1 - x0 - 1.0f);
    int yi0 = (int)floorf(ys); int yi1 = min(yi0 + 1, HP_S - 1);
    int xi0 = (int)floorf(xs); int xi1 = min(xi0 + 1, HP_S - 1);
    float wy = ys - (float)yi0;
    float wx = xs - (float)xi0;
    float c00 = (1.f - wy) * (1.f - wx);
    float c01 = (1.f - wy) * wx;
    float c10 = wy * (1.f - wx);
    float c11 = wy * wx;

#pragma unroll
    for (int c = 0; c < 3; c++) {
        const float* xb = x + ((size_t)b * 3 + c) * IM_S * IM_S;
        float v = fetchpix(xb, yi0, xi0) * c00
                + fetchpix(xb, yi0, xi1) * c01
                + fetchpix(xb, yi1, xi0) * c10
                + fetchpix(xb, yi1, xi1) * c11;
        out[(((size_t)crop * 3 + c) * OUT_S + oy) * OUT_S + ox] = v;
    }
}

// =========================================================================
extern "C" void kernel_launch(void* const* d_in, const int* in_sizes, int n_in,
                              void* d_out, int out_size)
{
    const float* x    = (const float*)d_in[0];
    const float* rpn  = (const float*)d_in[1];
    const float* w1   = (const float*)d_in[2];
    const float* b1   = (const float*)d_in[3];
    const float* w2   = (const float*)d_in[4];
    const float* b2   = (const float*)d_in[5];
    const float* w3   = (const float*)d_in[6];
    const float* b3   = (const float*)d_in[7];
    const float* wt1  = (const float*)d_in[8];
    const float* bt1  = (const float*)d_in[9];
    const float* wt2  = (const float*)d_in[10];
    const float* bt2  = (const float*)d_in[11];
    const float* wt3  = (const float*)d_in[12];
    const float* bt3  = (const float*)d_in[13];
    const int*   anc  = (const int*)d_in[14];
    float* out = (float*)d_out;

    conv1_kernel<<<dim3(KSPLIT, 2, BATCH), 224>>>(rpn, w1);
    finalize1_kernel<<<(NP1 + 255) / 256, 256>>>(b1);
    conv2_kernel<<<dim3((N2 + 255) / 256, KS2), 256>>>(w2);
    reduce2_kernel<<<(N2 + 255) / 256, 256>>>(b2);
    conv3_kernel<<<dim3((N3 + 255) / 256, KS3), 256>>>(w3);
    reduce3_kernel<<<(N3 + 255) / 256, 256>>>(b3);
    tidy_kernel<<<(BATCH * NA + 255) / 256, 256>>>(wt1, bt1, wt2, bt2, wt3, bt3, out);
    nms_kernel<<<BATCH, 256>>>(anc, out);
    crop_kernel<<<dim3(BATCH * TOPN, OUT_S), OUT_S>>>(x, anc, out);
}

// round 8
// speedup vs baseline: 2.2029x; 2.0155x over previous
#include <cuda_runtime.h>
#include <cuda_bf16.h>
#include <math.h>
#include <stdint.h>

// ---------------- problem constants ----------------
#define BATCH   16
#define TOPN    4
#define NA      1614
#define OUT_S   224
#define IM_S    448
#define PAD_S   224
#define HP_S    896

#define NPART   (BATCH*TOPN*3*OUT_S*OUT_S)   // 9,633,792
#define OFF_TIDX  NPART
#define OFF_TPROB (NPART + BATCH*TOPN)
#define OFF_SCORE (NPART + 2*BATCH*TOPN)

// conv1 (mma.sync tensor-core path, baseline PTX -- no 'a'-gated instrs)
#define KSPLIT  9                  // 9 x 16 = 144 CTAs ~ one wave
#define KCTA    2048               // K per CTA (18432 / 9)
#define NCHUNK  32                 // KCTA / 64
#define NP1     (BATCH*128*196)    // 401,408

// conv2/conv3 split-K
#define KS2     4
#define KS3     8
#define N2      (BATCH*128*49)
#define N3      (BATCH*128*16)

// ---------------- scratch ----------------
__device__ float g_part1[(size_t)KSPLIT * NP1];
__device__ float g_d1[NP1];
__device__ float g_p2[(size_t)KS2 * N2];
__device__ float g_d2[N2];
__device__ float g_p3[(size_t)KS3 * N3];
__device__ float g_d3[N3];
__device__ float g_score[BATCH*NA];
__device__ int   g_topidx[BATCH*TOPN];

__device__ __forceinline__ float neg_inf() { return __int_as_float(0xff800000); }

__device__ __forceinline__ uint32_t smem_to_u32(const void* p) {
    uint32_t a;
    asm("{ .reg .u64 t; cvta.to.shared.u64 t, %1; cvt.u32.u64 %0, t; }"
        : "=r"(a) : "l"(p));
    return a;
}
__device__ __forceinline__ uint32_t pkbf(__nv_bfloat16 a, __nv_bfloat16 b) {
    return (uint32_t)__bfloat16_as_ushort(a) | ((uint32_t)__bfloat16_as_ushort(b) << 16);
}

// ldmatrix wrappers (baseline PTX, sm_75+)
__device__ __forceinline__ void ldsm_x4(uint32_t& r0, uint32_t& r1, uint32_t& r2, uint32_t& r3,
                                        uint32_t addr) {
    asm volatile("ldmatrix.sync.aligned.m8n8.x4.shared.b16 {%0,%1,%2,%3}, [%4];"
                 : "=r"(r0), "=r"(r1), "=r"(r2), "=r"(r3) : "r"(addr));
}
__device__ __forceinline__ void ldsm_x2(uint32_t& r0, uint32_t& r1, uint32_t addr) {
    asm volatile("ldmatrix.sync.aligned.m8n8.x2.shared.b16 {%0,%1}, [%2];"
                 : "=r"(r0), "=r"(r1) : "r"(addr));
}
// mma.sync m16n8k16 bf16 -> f32 (baseline PTX, sm_80+)
__device__ __forceinline__ void mma16816(float* c, uint32_t a0, uint32_t a1, uint32_t a2,
                                         uint32_t a3, uint32_t b0, uint32_t b1) {
    asm volatile("mma.sync.aligned.m16n8k16.row.col.f32.bf16.bf16.f32 "
                 "{%0,%1,%2,%3}, {%4,%5,%6,%7}, {%8,%9}, {%0,%1,%2,%3};"
                 : "+f"(c[0]), "+f"(c[1]), "+f"(c[2]), "+f"(c[3])
                 : "r"(a0), "r"(a1), "r"(a2), "r"(a3), "r"(b0), "r"(b1));
}

// ---------------- dummies (shift ncu capture slot onto conv1_mma) --------
__global__ void dummy_kernel() {}

// ================= conv1 via mma.sync: 2048->128, 3x3, pad 1, 14x14 ======
// D[128 oc][224 n] += W[oc][k] * Im2col[n][k].  Per CTA: K = 2048, 32 chunks
// of 64. 2-term bf16 split: D = Ah*Bh + Ah*Bl + Al*Bh (fp32 accum).
// SMEM rows padded to 72 bf16 (144 B) for conflict-free ldmatrix.
#define SM_AH   0
#define SM_AL   18432
#define SM_BH   36864
#define SM_BL   69120
#define SM_TOT  101376

__global__ void __launch_bounds__(256) conv1_mma(const float* __restrict__ rpn,
                                                 const float* __restrict__ w)
{
    extern __shared__ __align__(16) char smem[];
    const uint32_t sb = smem_to_u32(smem);
    const int tid = threadIdx.x, wid = tid >> 5, lane = tid & 31;
    const int ks = blockIdx.x, b = blockIdx.y;
    const int k0base = ks * KCTA;
    const float* __restrict__ inb = rpn + (size_t)b * 2048 * 196;

    const int mrow = wid & 3;    // oc block: mrow*32 .. +31
    const int ncol = wid >> 2;   // n block:  ncol*112 .. +111

    float acc[2][14][4];
#pragma unroll
    for (int mt = 0; mt < 2; mt++)
#pragma unroll
        for (int nt = 0; nt < 14; nt++)
#pragma unroll
            for (int i = 0; i < 4; i++) acc[mt][nt][i] = 0.f;

    // ldmatrix per-lane address components
    const uint32_t aRow = (uint32_t)(lane & 15);         // row within 16-row tile
    const uint32_t aHalf = (uint32_t)(lane >> 4) * 16;   // k-half byte offset
    const uint32_t bRow = (uint32_t)(lane & 7);
    const uint32_t bHalf = (uint32_t)((lane >> 3) & 1) * 16;

    for (int c = 0; c < NCHUNK; c++) {
        const int k0 = k0base + c * 64;

        // ---- fill A tiles: weights [128 oc][64 k] fp32 -> bf16 hi/lo ----
        for (int pe = tid; pe < 4096; pe += 256) {
            int oc = pe >> 5, kk = (pe & 31) * 2;
            float2 v = *(const float2*)&w[(size_t)oc * 18432 + k0 + kk];
            __nv_bfloat16 h0 = __float2bfloat16_rn(v.x);
            __nv_bfloat16 h1 = __float2bfloat16_rn(v.y);
            __nv_bfloat16 l0 = __float2bfloat16_rn(v.x - __bfloat162float(h0));
            __nv_bfloat16 l1 = __float2bfloat16_rn(v.y - __bfloat162float(h1));
            uint32_t off = (uint32_t)(oc * 144 + kk * 2);
            *(uint32_t*)(smem + SM_AH + off) = pkbf(h0, h1);
            *(uint32_t*)(smem + SM_AL + off) = pkbf(l0, l1);
        }
        // ---- fill B tiles: im2col [224 n][64 k] -> bf16 hi/lo ----
        for (int pe = tid; pe < 7168; pe += 256) {
            int n = pe >> 5, kk = (pe & 31) * 2;
            int y = n >> 4, x = n & 15;
            int k = k0 + kk;
            float v0 = 0.f, v1 = 0.f;
            {
                int ic = k / 9, t = k - ic * 9;
                int iy = y + t / 3 - 1, ix = x + (t % 3) - 1;
                if ((unsigned)iy < 14u && (unsigned)ix < 14u)
                    v0 = __ldg(&inb[(size_t)ic * 196 + iy * 14 + ix]);
            }
            {
                int k1 = k + 1, ic = k1 / 9, t = k1 - ic * 9;
                int iy = y + t / 3 - 1, ix = x + (t % 3) - 1;
                if ((unsigned)iy < 14u && (unsigned)ix < 14u)
                    v1 = __ldg(&inb[(size_t)ic * 196 + iy * 14 + ix]);
            }
            __nv_bfloat16 h0 = __float2bfloat16_rn(v0);
            __nv_bfloat16 h1 = __float2bfloat16_rn(v1);
            __nv_bfloat16 l0 = __float2bfloat16_rn(v0 - __bfloat162float(h0));
            __nv_bfloat16 l1 = __float2bfloat16_rn(v1 - __bfloat162float(h1));
            uint32_t off = (uint32_t)(n * 144 + kk * 2);
            *(uint32_t*)(smem + SM_BH + off) = pkbf(h0, h1);
            *(uint32_t*)(smem + SM_BL + off) = pkbf(l0, l1);
        }
        __syncthreads();

        // ---- 4 k-steps of m16n8k16 ----
#pragma unroll
        for (int kkstep = 0; kkstep < 4; kkstep++) {
            const uint32_t kb = (uint32_t)kkstep * 32;   // byte offset of k-step
            uint32_t ah[2][4], al[2][4];
#pragma unroll
            for (int mt = 0; mt < 2; mt++) {
                uint32_t ra = (uint32_t)((mrow * 32 + mt * 16 + aRow) * 144) + kb + aHalf;
                ldsm_x4(ah[mt][0], ah[mt][1], ah[mt][2], ah[mt][3], sb + SM_AH + ra);
                ldsm_x4(al[mt][0], al[mt][1], al[mt][2], al[mt][3], sb + SM_AL + ra);
            }
#pragma unroll
            for (int nt = 0; nt < 14; nt++) {
                uint32_t rb = (uint32_t)((ncol * 112 + nt * 8 + bRow) * 144) + kb + bHalf;
                uint32_t bh0, bh1, bl0, bl1;
                ldsm_x2(bh0, bh1, sb + SM_BH + rb);
                ldsm_x2(bl0, bl1, sb + SM_BL + rb);
#pragma unroll
                for (int mt = 0; mt < 2; mt++) {
                    mma16816(acc[mt][nt], ah[mt][0], ah[mt][1], ah[mt][2], ah[mt][3], bh0, bh1);
                    mma16816(acc[mt][nt], ah[mt][0], ah[mt][1], ah[mt][2], ah[mt][3], bl0, bl1);
                    mma16816(acc[mt][nt], al[mt][0], al[mt][1], al[mt][2], al[mt][3], bh0, bh1);
                }
            }
        }
        __syncthreads();
    }

    // ---- epilogue: scatter fp32 partials ----
    const int r = lane >> 2, q = lane & 3;
    float* pp = g_part1 + (size_t)ks * NP1 + ((size_t)b * 128) * 196;
#pragma unroll
    for (int mt = 0; mt < 2; mt++) {
        int oc0 = mrow * 32 + mt * 16 + r;
#pragma unroll
        for (int nt = 0; nt < 14; nt++) {
            int n0 = ncol * 112 + nt * 8 + 2 * q;
            int y0 = n0 >> 4, x0 = n0 & 15;
            int y1 = (n0 + 1) >> 4, x1 = (n0 + 1) & 15;
            if (x0 < 14) {
                pp[(size_t)oc0 * 196 + y0 * 14 + x0]       = acc[mt][nt][0];
                pp[(size_t)(oc0 + 8) * 196 + y0 * 14 + x0] = acc[mt][nt][2];
            }
            if (x1 < 14) {
                pp[(size_t)oc0 * 196 + y1 * 14 + x1]       = acc[mt][nt][1];
                pp[(size_t)(oc0 + 8) * 196 + y1 * 14 + x1] = acc[mt][nt][3];
            }
        }
    }
}

// deterministic split-K reduce + bias + relu
__global__ void finalize1_kernel(const float* __restrict__ bias)
{
    int n = blockIdx.x * 256 + threadIdx.x;
    if (n >= NP1) return;
    float s = 0.f;
#pragma unroll
    for (int k = 0; k < KSPLIT; k++) s += g_part1[(size_t)k * NP1 + n];
    int oc = (n / 196) & 127;
    g_d1[n] = fmaxf(s + __ldg(&bias[oc]), 0.f);
}

// ================= conv2: 128->128, 3x3, stride 2, pad 1 (14->7) =========
__global__ void conv2_kernel(const float* __restrict__ w)
{
    int n = blockIdx.x * 256 + threadIdx.x;
    if (n >= N2) return;
    const int ks = blockIdx.y;
    int p = n % 49, oc = (n / 49) & 127, b = n / (49 * 128);
    int oy = p / 7, ox = p % 7;
    const int icb = ks * 32;
    const float* ib = g_d1 + (size_t)b * 128 * 196 + (size_t)icb * 196;
    const float* wb = w + (size_t)oc * 1152 + (size_t)icb * 9;
    float a0 = 0.f, a1 = 0.f, a2 = 0.f, a3 = 0.f;
#pragma unroll
    for (int ky = 0; ky < 3; ky++) {
        int iy = 2 * oy + ky - 1;
        if (iy < 0 || iy >= 14) continue;
#pragma unroll
        for (int kx = 0; kx < 3; kx++) {
            int ix = 2 * ox + kx - 1;
            if (ix < 0 || ix >= 14) continue;
            const float* ip = ib + iy * 14 + ix;
            const float* wp = wb + ky * 3 + kx;
#pragma unroll 8
            for (int ic = 0; ic < 32; ic += 4) {
                a0 = fmaf(__ldg(&ip[(size_t)(ic + 0) * 196]), __ldg(&wp[(size_t)(ic + 0) * 9]), a0);
                a1 = fmaf(__ldg(&ip[(size_t)(ic + 1) * 196]), __ldg(&wp[(size_t)(ic + 1) * 9]), a1);
                a2 = fmaf(__ldg(&ip[(size_t)(ic + 2) * 196]), __ldg(&wp[(size_t)(ic + 2) * 9]), a2);
                a3 = fmaf(__ldg(&ip[(size_t)(ic + 3) * 196]), __ldg(&wp[(size_t)(ic + 3) * 9]), a3);
            }
        }
    }
    g_p2[(size_t)ks * N2 + n] = (a0 + a1) + (a2 + a3);
}

__global__ void reduce2_kernel(const float* __restrict__ bias)
{
    int n = blockIdx.x * 256 + threadIdx.x;
    if (n >= N2) return;
    float s = __ldg(&bias[(n / 49) & 127]);
#pragma unroll
    for (int k = 0; k < KS2; k++) s += g_p2[(size_t)k * N2 + n];
    g_d2[n] = fmaxf(s, 0.f);
}

// ================= conv3: 128->128, 3x3, stride 2, pad 1 (7->4) ==========
__global__ void conv3_kernel(const float* __restrict__ w)
{
    int n = blockIdx.x * 256 + threadIdx.x;
    if (n >= N3) return;
    const int ks = blockIdx.y;
    int p = n % 16, oc = (n / 16) & 127, b = n / (16 * 128);
    int oy = p / 4, ox = p % 4;
    const int icb = ks * 16;
    const float* ib = g_d2 + (size_t)b * 128 * 49 + (size_t)icb * 49;
    const float* wb = w + (size_t)oc * 1152 + (size_t)icb * 9;
    float a0 = 0.f, a1 = 0.f, a2 = 0.f, a3 = 0.f;
#pragma unroll
    for (int ky = 0; ky < 3; ky++) {
        int iy = 2 * oy + ky - 1;
        if (iy < 0 || iy >= 7) continue;
#pragma unroll
        for (int kx = 0; kx < 3; kx++) {
            int ix = 2 * ox + kx - 1;
            if (ix < 0 || ix >= 7) continue;
            const float* ip = ib + iy * 7 + ix;
            const float* wp = wb + ky * 3 + kx;
#pragma unroll 4
            for (int ic = 0; ic < 16; ic += 4) {
                a0 = fmaf(__ldg(&ip[(size_t)(ic + 0) * 49]), __ldg(&wp[(size_t)(ic + 0) * 9]), a0);
                a1 = fmaf(__ldg(&ip[(size_t)(ic + 1) * 49]), __ldg(&wp[(size_t)(ic + 1) * 9]), a1);
                a2 = fmaf(__ldg(&ip[(size_t)(ic + 2) * 49]), __ldg(&wp[(size_t)(ic + 2) * 9]), a2);
                a3 = fmaf(__ldg(&ip[(size_t)(ic + 3) * 49]), __ldg(&wp[(size_t)(ic + 3) * 9]), a3);
            }
        }
    }
    g_p3[(size_t)ks * N3 + n] = (a0 + a1) + (a2 + a3);
}

__global__ void reduce3_kernel(const float* __restrict__ bias)
{
    int n = blockIdx.x * 256 + threadIdx.x;
    if (n >= N3) return;
    float s = __ldg(&bias[(n / 16) & 127]);
#pragma unroll
    for (int k = 0; k < KS3; k++) s += g_p3[(size_t)k * N3 + n];
    g_d3[n] = fmaxf(s, 0.f);
}

// ================= tidy 1x1 convs -> concatenated scores =================
__global__ void tidy_kernel(const float* __restrict__ wt1, const float* __restrict__ bt1,
                            const float* __restrict__ wt2, const float* __restrict__ bt2,
                            const float* __restrict__ wt3, const float* __restrict__ bt3,
                            float* __restrict__ out)
{
    int n = blockIdx.x * 256 + threadIdx.x;
    if (n >= BATCH * NA) return;
    int b = n / NA, j = n % NA;
    const float* src; const float* wt; float bias; int c, p, stride;
    if (j < 1176) {
        c = j / 196; p = j % 196;
        src = g_d1 + (size_t)b * 128 * 196; stride = 196;
        wt = wt1; bias = __ldg(&bt1[c]);
    } else if (j < 1470) {
        int jj = j - 1176; c = jj / 49; p = jj % 49;
        src = g_d2 + (size_t)b * 128 * 49; stride = 49;
        wt = wt2; bias = __ldg(&bt2[c]);
    } else {
        int jj = j - 1470; c = jj / 16; p = jj % 16;
        src = g_d3 + (size_t)b * 128 * 16; stride = 16;
        wt = wt3; bias = __ldg(&bt3[c]);
    }
    const float4* wv = (const float4*)(wt + (size_t)c * 128);
    float a0 = 0.f, a1 = 0.f, a2 = 0.f, a3 = 0.f;
#pragma unroll 8
    for (int i = 0; i < 32; i++) {
        float4 w4 = __ldg(&wv[i]);
        int ic = 4 * i;
        a0 = fmaf(src[(size_t)(ic + 0) * stride + p], w4.x, a0);
        a1 = fmaf(src[(size_t)(ic + 1) * stride + p], w4.y, a1);
        a2 = fmaf(src[(size_t)(ic + 2) * stride + p], w4.z, a2);
        a3 = fmaf(src[(size_t)(ic + 3) * stride + p], w4.w, a3);
    }
    float acc = bias + ((a0 + a1) + (a2 + a3));
    g_score[n] = acc;
    out[OFF_SCORE + n] = acc;
}

// ================= greedy NMS ==============================================
__global__ void nms_kernel(const int* __restrict__ anchors, float* __restrict__ out)
{
    int b = blockIdx.x, tid = threadIdx.x;
    __shared__ float s[NA];
    __shared__ float rv[256];
    __shared__ int   ri[256];
    __shared__ float pbox[4];
    __shared__ float parea;

    for (int j = tid; j < NA; j += 256) s[j] = g_score[b * NA + j];
    __syncthreads();

    for (int k = 0; k < TOPN; k++) {
        float bv = neg_inf(); int bi = 0x7fffffff;
        for (int j = tid; j < NA; j += 256) {
            float v = s[j];
            if (v > bv || (v == bv && j < bi)) { bv = v; bi = j; }
        }
        rv[tid] = bv; ri[tid] = bi;
        __syncthreads();
        for (int st = 128; st > 0; st >>= 1) {
            if (tid < st) {
                float v2 = rv[tid + st]; int i2 = ri[tid + st];
                if (v2 > rv[tid] || (v2 == rv[tid] && i2 < ri[tid])) {
                    rv[tid] = v2; ri[tid] = i2;
                }
            }
            __syncthreads();
        }
        if (tid == 0) {
            int pick = ri[0];
            const int* a = anchors + (size_t)pick * 4;
            pbox[0] = (float)a[0]; pbox[1] = (float)a[1];
            pbox[2] = (float)a[2]; pbox[3] = (float)a[3];
            parea = (pbox[2] - pbox[0]) * (pbox[3] - pbox[1]);
            g_topidx[b * TOPN + k] = pick;
            out[OFF_TIDX  + b * TOPN + k] = (float)pick;
            out[OFF_TPROB + b * TOPN + k] = rv[0];
        }
        __syncthreads();
        float y0 = pbox[0], x0 = pbox[1], y1 = pbox[2], x1 = pbox[3], pa = parea;
        for (int j = tid; j < NA; j += 256) {
            const int* a = anchors + (size_t)j * 4;
            float ay0 = (float)a[0], ax0 = (float)a[1];
            float ay1 = (float)a[2], ax1 = (float)a[3];
            float iy = fmaxf(fminf(ay1, y1) - fmaxf(ay0, y0), 0.f);
            float ix = fmaxf(fminf(ax1, x1) - fmaxf(ax0, x0), 0.f);
            float inter = iy * ix;
            float area  = (ay1 - ay0) * (ax1 - ax0);
            float iou = inter / (area + pa - inter);
            if (iou >= 0.25f) s[j] = neg_inf();
        }
        __syncthreads();
    }
}

// ================= crop + bilinear resize =================================
__device__ __forceinline__ float fetchpix(const float* __restrict__ xb, int yy, int xx)
{
    yy -= PAD_S; xx -= PAD_S;
    if ((unsigned)yy < (unsigned)IM_S && (unsigned)xx < (unsigned)IM_S)
        return __ldg(&xb[(size_t)yy * IM_S + xx]);
    return 0.f;
}

__global__ void crop_kernel(const float* __restrict__ x,
                            const int* __restrict__ anchors,
                            float* __restrict__ out)
{
    const int crop = blockIdx.x;
    const int oy   = blockIdx.y;
    const int ox   = threadIdx.x;
    const int b    = crop >> 2;

    const int pick = g_topidx[crop];
    const int* a = anchors + (size_t)pick * 4;
    float y0 = (float)a[0], x0 = (float)a[1], y1 = (float)a[2], x1 = (float)a[3];

    float ty = (float)oy / 223.0f;
    float tx = (float)ox / 223.0f;
    float ys = y0 + ty * (y1 - y0 - 1.0f);
    float xs = x0 + tx * (x1 - x0 - 1.0f);
    int yi0 = (int)floorf(ys); int yi1 = min(yi0 + 1, HP_S - 1);
    int xi0 = (int)floorf(xs); int xi1 = min(xi0 + 1, HP_S - 1);
    float wy = ys - (float)yi0;
    float wx = xs - (float)xi0;
    float c00 = (1.f - wy) * (1.f - wx);
    float c01 = (1.f - wy) * wx;
    float c10 = wy * (1.f - wx);
    float c11 = wy * wx;

#pragma unroll
    for (int c = 0; c < 3; c++) {
        const float* xb = x + ((size_t)b * 3 + c) * IM_S * IM_S;
        float v = fetchpix(xb, yi0, xi0) * c00
                + fetchpix(xb, yi0, xi1) * c01
                + fetchpix(xb, yi1, xi0) * c10
                + fetchpix(xb, yi1, xi1) * c11;
        out[(((size_t)crop * 3 + c) * OUT_S + oy) * OUT_S + ox] = v;
    }
}

// =========================================================================
extern "C" void kernel_launch(void* const* d_in, const int* in_sizes, int n_in,
                              void* d_out, int out_size)
{
    const float* x    = (const float*)d_in[0];
    const float* rpn  = (const float*)d_in[1];
    const float* w1   = (const float*)d_in[2];
    const float* b1   = (const float*)d_in[3];
    const float* w2   = (const float*)d_in[4];
    const float* b2   = (const float*)d_in[5];
    const float* w3   = (const float*)d_in[6];
    const float* b3   = (const float*)d_in[7];
    const float* wt1  = (const float*)d_in[8];
    const float* bt1  = (const float*)d_in[9];
    const float* wt2  = (const float*)d_in[10];
    const float* bt2  = (const float*)d_in[11];
    const float* wt3  = (const float*)d_in[12];
    const float* bt3  = (const float*)d_in[13];
    const int*   anc  = (const int*)d_in[14];
    float* out = (float*)d_out;

    cudaFuncSetAttribute(conv1_mma, cudaFuncAttributeMaxDynamicSharedMemorySize, SM_TOT);

    // 3 dummies so ncu's fixed capture slot (4th launch) lands on conv1_mma
    dummy_kernel<<<1, 32>>>();
    dummy_kernel<<<1, 32>>>();
    dummy_kernel<<<1, 32>>>();

    conv1_mma<<<dim3(KSPLIT, BATCH), 256, SM_TOT>>>(rpn, w1);
    finalize1_kernel<<<(NP1 + 255) / 256, 256>>>(b1);
    conv2_kernel<<<dim3((N2 + 255) / 256, KS2), 256>>>(w2);
    reduce2_kernel<<<(N2 + 255) / 256, 256>>>(b2);
    conv3_kernel<<<dim3((N3 + 255) / 256, KS3), 256>>>(w3);
    reduce3_kernel<<<(N3 + 255) / 256, 256>>>(b3);
    tidy_kernel<<<(BATCH * NA + 255) / 256, 256>>>(wt1, bt1, wt2, bt2, wt3, bt3, out);
    nms_kernel<<<BATCH, 256>>>(anc, out);
    crop_kernel<<<dim3(BATCH * TOPN, OUT_S), OUT_S>>>(x, anc, out);
}

// round 9
// speedup vs baseline: 3.9364x; 1.7869x over previous
#include <cuda_runtime.h>
#include <cuda_bf16.h>
#include <math.h>
#include <stdint.h>

// ---------------- problem constants ----------------
#define BATCH   16
#define TOPN    4
#define NA      1614
#define OUT_S   224
#define IM_S    448
#define PAD_S   224
#define HP_S    896

#define NPART   (BATCH*TOPN*3*OUT_S*OUT_S)   // 9,633,792
#define OFF_TIDX  NPART
#define OFF_TPROB (NPART + BATCH*TOPN)
#define OFF_SCORE (NPART + 2*BATCH*TOPN)

// conv1: K split tap-major -- one tap (of 9) per CTA-column, K=2048 ic each
#define KSPLIT  9
#define NCHUNK  32                 // 2048 ic / 64 per chunk
#define NP1     (BATCH*128*196)    // 401,408

// conv2/conv3 split-K
#define KS2     4
#define KS3     8
#define N2      (BATCH*128*49)
#define N3      (BATCH*128*16)

// ---------------- scratch ----------------
__device__ float g_part1[(size_t)KSPLIT * NP1];
__device__ float g_d1[NP1];
__device__ float g_p2[(size_t)KS2 * N2];
__device__ float g_d2[N2];
__device__ float g_p3[(size_t)KS3 * N3];
__device__ float g_d3[N3];
__device__ float g_score[BATCH*NA];
__device__ int   g_topidx[BATCH*TOPN];

// bf16 hi/lo prepped operands
__device__ __nv_bfloat16 g_wh[(size_t)9 * 128 * 2048];   // [tap][oc][ic]
__device__ __nv_bfloat16 g_wl[(size_t)9 * 128 * 2048];
__device__ __nv_bfloat16 g_ih[(size_t)BATCH * 288 * 2048]; // [b][pos 16x18][ic]
__device__ __nv_bfloat16 g_il[(size_t)BATCH * 288 * 2048];

__device__ __forceinline__ float neg_inf() { return __int_as_float(0xff800000); }

__device__ __forceinline__ uint32_t smem_to_u32(const void* p) {
    uint32_t a;
    asm("{ .reg .u64 t; cvta.to.shared.u64 t, %1; cvt.u32.u64 %0, t; }"
        : "=r"(a) : "l"(p));
    return a;
}
__device__ __forceinline__ void cpa16(uint32_t dst, const void* src) {
    asm volatile("cp.async.cg.shared.global [%0], [%1], 16;"
                 :: "r"(dst), "l"(src) : "memory");
}
// ldmatrix wrappers (baseline PTX, sm_75+)
__device__ __forceinline__ void ldsm_x4(uint32_t& r0, uint32_t& r1, uint32_t& r2, uint32_t& r3,
                                        uint32_t addr) {
    asm volatile("ldmatrix.sync.aligned.m8n8.x4.shared.b16 {%0,%1,%2,%3}, [%4];"
                 : "=r"(r0), "=r"(r1), "=r"(r2), "=r"(r3) : "r"(addr));
}
__device__ __forceinline__ void ldsm_x2(uint32_t& r0, uint32_t& r1, uint32_t addr) {
    asm volatile("ldmatrix.sync.aligned.m8n8.x2.shared.b16 {%0,%1}, [%2];"
                 : "=r"(r0), "=r"(r1) : "r"(addr));
}
// mma.sync m16n8k16 bf16 -> f32 (baseline PTX, sm_80+)
__device__ __forceinline__ void mma16816(float* c, uint32_t a0, uint32_t a1, uint32_t a2,
                                         uint32_t a3, uint32_t b0, uint32_t b1) {
    asm volatile("mma.sync.aligned.m16n8k16.row.col.f32.bf16.bf16.f32 "
                 "{%0,%1,%2,%3}, {%4,%5,%6,%7}, {%8,%9}, {%0,%1,%2,%3};"
                 : "+f"(c[0]), "+f"(c[1]), "+f"(c[2]), "+f"(c[3])
                 : "r"(a0), "r"(a1), "r"(a2), "r"(a3), "r"(b0), "r"(b1));
}

__global__ void dummy_kernel() {}

// ================= prep_w: w1 fp32 -> bf16 hi/lo, tap-major layout =========
__global__ void prep_w(const float* __restrict__ w)
{
    int idx = blockIdx.x * 256 + threadIdx.x;     // one thread per (oc, ic)
    if (idx >= 128 * 2048) return;
    int oc = idx >> 11, ic = idx & 2047;
    const float* src = w + (size_t)oc * 18432 + (size_t)ic * 9;
#pragma unroll
    for (int t = 0; t < 9; t++) {
        float v = __ldg(&src[t]);
        __nv_bfloat16 h = __float2bfloat16_rn(v);
        __nv_bfloat16 l = __float2bfloat16_rn(v - __bfloat162float(h));
        size_t d = ((size_t)t * 128 + oc) * 2048 + ic;
        g_wh[d] = h;
        g_wl[d] = l;
    }
}

// ================= prep_in: rpn fp32 -> bf16 hi/lo transposed padded planes
// dest [b][pos][ic], pos = py*18+px over a 16x18 zero-padded 14x14 window.
__global__ void prep_in(const float* __restrict__ in)
{
    __shared__ float s_in[32][197];
    const int icb = blockIdx.x;          // 0..63 (32 ic each)
    const int b   = blockIdx.y;
    const int tid = threadIdx.x;

    const float* src = in + ((size_t)b * 2048 + icb * 32) * 196;
    for (int i = tid; i < 32 * 196; i += 256)
        s_in[i / 196][i % 196] = __ldg(&src[i]);
    __syncthreads();

    for (int i = tid; i < 288 * 16; i += 256) {
        int pos = i >> 4, icp = i & 15;
        int py = pos / 18, px = pos % 18;
        int iy = py - 1, ix = px - 1;
        float v0 = 0.f, v1 = 0.f;
        if ((unsigned)iy < 14u && (unsigned)ix < 14u) {
            v0 = s_in[icp * 2][iy * 14 + ix];
            v1 = s_in[icp * 2 + 1][iy * 14 + ix];
        }
        __nv_bfloat16 h0 = __float2bfloat16_rn(v0);
        __nv_bfloat16 h1 = __float2bfloat16_rn(v1);
        __nv_bfloat16 l0 = __float2bfloat16_rn(v0 - __bfloat162float(h0));
        __nv_bfloat16 l1 = __float2bfloat16_rn(v1 - __bfloat162float(h1));
        size_t d = ((size_t)b * 288 + pos) * 2048 + icb * 32 + icp * 2;
        *(uint32_t*)&g_ih[d] = (uint32_t)__bfloat16_as_ushort(h0) |
                               ((uint32_t)__bfloat16_as_ushort(h1) << 16);
        *(uint32_t*)&g_il[d] = (uint32_t)__bfloat16_as_ushort(l0) |
                               ((uint32_t)__bfloat16_as_ushort(l1) << 16);
    }
}

// ================= conv1 via mma.sync, cp.async double-buffered ===========
// D[128 oc][224 n] per (tap, batch) CTA; K = 2048 ic, 32 chunks of 64.
// 2-term bf16 split: D = Ah*Bh + Ah*Bl + Al*Bh (fp32 accum).
// SMEM rows: 64 bf16 data padded to 72 (144 B) for conflict-free ldmatrix.
#define SA_H   0
#define SA_L   18432
#define SB_H   36864
#define SB_L   69120
#define STG_SZ 101376
#define SM_TOT (2 * STG_SZ)

__global__ void __launch_bounds__(256) conv1_mma()
{
    extern __shared__ __align__(16) char smem[];
    const uint32_t sb = smem_to_u32(smem);
    const int tid = threadIdx.x, wid = tid >> 5, lane = tid & 31;
    const int t = blockIdx.x, b = blockIdx.y;
    const int dy = t / 3 - 1, dx = t % 3 - 1;

    const int mrow = wid & 3;    // oc block: mrow*32 .. +31
    const int ncol = wid >> 2;   // n block:  ncol*112 .. +111

    float acc[2][14][4];
#pragma unroll
    for (int mt = 0; mt < 2; mt++)
#pragma unroll
        for (int nt = 0; nt < 14; nt++)
#pragma unroll
            for (int i = 0; i < 4; i++) acc[mt][nt][i] = 0.f;

    const __nv_bfloat16* ah0 = g_wh + ((size_t)t * 128) * 2048;
    const __nv_bfloat16* al0 = g_wl + ((size_t)t * 128) * 2048;
    const __nv_bfloat16* bh0 = g_ih + (size_t)b * 288 * 2048;
    const __nv_bfloat16* bl0 = g_il + (size_t)b * 288 * 2048;

    auto fill = [&](int stage, int c) {
        const uint32_t s0 = sb + stage * STG_SZ;
        const int kof = c * 64;
        for (int idx = tid; idx < 1024; idx += 256) {
            int row = idx >> 3, seg = idx & 7;
            uint32_t off = (uint32_t)(row * 144 + seg * 16);
            size_t so = (size_t)row * 2048 + kof + seg * 8;
            cpa16(s0 + SA_H + off, ah0 + so);
            cpa16(s0 + SA_L + off, al0 + so);
        }
        for (int idx = tid; idx < 1792; idx += 256) {
            int row = idx >> 3, seg = idx & 7;
            int y = row >> 4, x = row & 15;
            int pos = (y + dy + 1) * 18 + (x + dx + 1);
            uint32_t off = (uint32_t)(row * 144 + seg * 16);
            size_t so = (size_t)pos * 2048 + kof + seg * 8;
            cpa16(s0 + SB_H + off, bh0 + so);
            cpa16(s0 + SB_L + off, bl0 + so);
        }
        asm volatile("cp.async.commit_group;" ::: "memory");
    };

    // ldmatrix per-lane address components
    const uint32_t aRow = (uint32_t)(lane & 15);
    const uint32_t aHalf = (uint32_t)(lane >> 4) * 16;
    const uint32_t bRow = (uint32_t)(lane & 7);
    const uint32_t bHalf = (uint32_t)((lane >> 3) & 1) * 16;

    fill(0, 0);
    int s = 0;
    for (int c = 0; c < NCHUNK; c++) {
        if (c + 1 < NCHUNK) {
            fill(s ^ 1, c + 1);
            asm volatile("cp.async.wait_group 1;" ::: "memory");
        } else {
            asm volatile("cp.async.wait_group 0;" ::: "memory");
        }
        __syncthreads();

        const uint32_t s0 = sb + s * STG_SZ;
#pragma unroll
        for (int kkstep = 0; kkstep < 4; kkstep++) {
            const uint32_t kb = (uint32_t)kkstep * 32;
            uint32_t ah[2][4], al[2][4];
#pragma unroll
            for (int mt = 0; mt < 2; mt++) {
                uint32_t ra = (uint32_t)((mrow * 32 + mt * 16 + aRow) * 144) + kb + aHalf;
                ldsm_x4(ah[mt][0], ah[mt][1], ah[mt][2], ah[mt][3], s0 + SA_H + ra);
                ldsm_x4(al[mt][0], al[mt][1], al[mt][2], al[mt][3], s0 + SA_L + ra);
            }
#pragma unroll
            for (int nt = 0; nt < 14; nt++) {
                uint32_t rb = (uint32_t)((ncol * 112 + nt * 8 + bRow) * 144) + kb + bHalf;
                uint32_t bh0r, bh1r, bl0r, bl1r;
                ldsm_x2(bh0r, bh1r, s0 + SB_H + rb);
                ldsm_x2(bl0r, bl1r, s0 + SB_L + rb);
#pragma unroll
                for (int mt = 0; mt < 2; mt++) {
                    mma16816(acc[mt][nt], ah[mt][0], ah[mt][1], ah[mt][2], ah[mt][3], bh0r, bh1r);
                    mma16816(acc[mt][nt], ah[mt][0], ah[mt][1], ah[mt][2], ah[mt][3], bl0r, bl1r);
                    mma16816(acc[mt][nt], al[mt][0], al[mt][1], al[mt][2], al[mt][3], bh0r, bh1r);
                }
            }
        }
        __syncthreads();
        s ^= 1;
    }

    // ---- epilogue: scatter fp32 partials ----
    const int r = lane >> 2, q = lane & 3;
    float* pp = g_part1 + (size_t)t * NP1 + ((size_t)b * 128) * 196;
#pragma unroll
    for (int mt = 0; mt < 2; mt++) {
        int oc0 = mrow * 32 + mt * 16 + r;
#pragma unroll
        for (int nt = 0; nt < 14; nt++) {
            int n0 = ncol * 112 + nt * 8 + 2 * q;
            int y0 = n0 >> 4, x0 = n0 & 15;
            int y1 = (n0 + 1) >> 4, x1 = (n0 + 1) & 15;
            if (x0 < 14) {
                pp[(size_t)oc0 * 196 + y0 * 14 + x0]       = acc[mt][nt][0];
                pp[(size_t)(oc0 + 8) * 196 + y0 * 14 + x0] = acc[mt][nt][2];
            }
            if (x1 < 14) {
                pp[(size_t)oc0 * 196 + y1 * 14 + x1]       = acc[mt][nt][1];
                pp[(size_t)(oc0 + 8) * 196 + y1 * 14 + x1] = acc[mt][nt][3];
            }
        }
    }
}

// deterministic split-K reduce + bias + relu
__global__ void finalize1_kernel(const float* __restrict__ bias)
{
    int n = blockIdx.x * 256 + threadIdx.x;
    if (n >= NP1) return;
    float s = 0.f;
#pragma unroll
    for (int k = 0; k < KSPLIT; k++) s += g_part1[(size_t)k * NP1 + n];
    int oc = (n / 196) & 127;
    g_d1[n] = fmaxf(s + __ldg(&bias[oc]), 0.f);
}

// ================= conv2: 128->128, 3x3, stride 2, pad 1 (14->7) =========
__global__ void conv2_kernel(const float* __restrict__ w)
{
    int n = blockIdx.x * 256 + threadIdx.x;
    if (n >= N2) return;
    const int ks = blockIdx.y;
    int p = n % 49, oc = (n / 49) & 127, b = n / (49 * 128);
    int oy = p / 7, ox = p % 7;
    const int icb = ks * 32;
    const float* ib = g_d1 + (size_t)b * 128 * 196 + (size_t)icb * 196;
    const float* wb = w + (size_t)oc * 1152 + (size_t)icb * 9;
    float a0 = 0.f, a1 = 0.f, a2 = 0.f, a3 = 0.f;
#pragma unroll
    for (int ky = 0; ky < 3; ky++) {
        int iy = 2 * oy + ky - 1;
        if (iy < 0 || iy >= 14) continue;
#pragma unroll
        for (int kx = 0; kx < 3; kx++) {
            int ix = 2 * ox + kx - 1;
            if (ix < 0 || ix >= 14) continue;
            const float* ip = ib + iy * 14 + ix;
            const float* wp = wb + ky * 3 + kx;
#pragma unroll 8
            for (int ic = 0; ic < 32; ic += 4) {
                a0 = fmaf(__ldg(&ip[(size_t)(ic + 0) * 196]), __ldg(&wp[(size_t)(ic + 0) * 9]), a0);
                a1 = fmaf(__ldg(&ip[(size_t)(ic + 1) * 196]), __ldg(&wp[(size_t)(ic + 1) * 9]), a1);
                a2 = fmaf(__ldg(&ip[(size_t)(ic + 2) * 196]), __ldg(&wp[(size_t)(ic + 2) * 9]), a2);
                a3 = fmaf(__ldg(&ip[(size_t)(ic + 3) * 196]), __ldg(&wp[(size_t)(ic + 3) * 9]), a3);
            }
        }
    }
    g_p2[(size_t)ks * N2 + n] = (a0 + a1) + (a2 + a3);
}

__global__ void reduce2_kernel(const float* __restrict__ bias)
{
    int n = blockIdx.x * 256 + threadIdx.x;
    if (n >= N2) return;
    float s = __ldg(&bias[(n / 49) & 127]);
#pragma unroll
    for (int k = 0; k < KS2; k++) s += g_p2[(size_t)k * N2 + n];
    g_d2[n] = fmaxf(s, 0.f);
}

// ================= conv3: 128->128, 3x3, stride 2, pad 1 (7->4) ==========
__global__ void conv3_kernel(const float* __restrict__ w)
{
    int n = blockIdx.x * 256 + threadIdx.x;
    if (n >= N3) return;
    const int ks = blockIdx.y;
    int p = n % 16, oc = (n / 16) & 127, b = n / (16 * 128);
    int oy = p / 4, ox = p % 4;
    const int icb = ks * 16;
    const float* ib = g_d2 + (size_t)b * 128 * 49 + (size_t)icb * 49;
    const float* wb = w + (size_t)oc * 1152 + (size_t)icb * 9;
    float a0 = 0.f, a1 = 0.f, a2 = 0.f, a3 = 0.f;
#pragma unroll
    for (int ky = 0; ky < 3; ky++) {
        int iy = 2 * oy + ky - 1;
        if (iy < 0 || iy >= 7) continue;
#pragma unroll
        for (int kx = 0; kx < 3; kx++) {
            int ix = 2 * ox + kx - 1;
            if (ix < 0 || ix >= 7) continue;
            const float* ip = ib + iy * 7 + ix;
            const float* wp = wb + ky * 3 + kx;
#pragma unroll 4
            for (int ic = 0; ic < 16; ic += 4) {
                a0 = fmaf(__ldg(&ip[(size_t)(ic + 0) * 49]), __ldg(&wp[(size_t)(ic + 0) * 9]), a0);
                a1 = fmaf(__ldg(&ip[(size_t)(ic + 1) * 49]), __ldg(&wp[(size_t)(ic + 1) * 9]), a1);
                a2 = fmaf(__ldg(&ip[(size_t)(ic + 2) * 49]), __ldg(&wp[(size_t)(ic + 2) * 9]), a2);
                a3 = fmaf(__ldg(&ip[(size_t)(ic + 3) * 49]), __ldg(&wp[(size_t)(ic + 3) * 9]), a3);
            }
        }
    }
    g_p3[(size_t)ks * N3 + n] = (a0 + a1) + (a2 + a3);
}

__global__ void reduce3_kernel(const float* __restrict__ bias)
{
    int n = blockIdx.x * 256 + threadIdx.x;
    if (n >= N3) return;
    float s = __ldg(&bias[(n / 16) & 127]);
#pragma unroll
    for (int k = 0; k < KS3; k++) s += g_p3[(size_t)k * N3 + n];
    g_d3[n] = fmaxf(s, 0.f);
}

// ================= tidy 1x1 convs -> concatenated scores =================
__global__ void tidy_kernel(const float* __restrict__ wt1, const float* __restrict__ bt1,
                            const float* __restrict__ wt2, const float* __restrict__ bt2,
                            const float* __restrict__ wt3, const float* __restrict__ bt3,
                            float* __restrict__ out)
{
    int n = blockIdx.x * 256 + threadIdx.x;
    if (n >= BATCH * NA) return;
    int b = n / NA, j = n % NA;
    const float* src; const float* wt; float bias; int c, p, stride;
    if (j < 1176) {
        c = j / 196; p = j % 196;
        src = g_d1 + (size_t)b * 128 * 196; stride = 196;
        wt = wt1; bias = __ldg(&bt1[c]);
    } else if (j < 1470) {
        int jj = j - 1176; c = jj / 49; p = jj % 49;
        src = g_d2 + (size_t)b * 128 * 49; stride = 49;
        wt = wt2; bias = __ldg(&bt2[c]);
    } else {
        int jj = j - 1470; c = jj / 16; p = jj % 16;
        src = g_d3 + (size_t)b * 128 * 16; stride = 16;
        wt = wt3; bias = __ldg(&bt3[c]);
    }
    const float4* wv = (const float4*)(wt + (size_t)c * 128);
    float a0 = 0.f, a1 = 0.f, a2 = 0.f, a3 = 0.f;
#pragma unroll 8
    for (int i = 0; i < 32; i++) {
        float4 w4 = __ldg(&wv[i]);
        int ic = 4 * i;
        a0 = fmaf(src[(size_t)(ic + 0) * stride + p], w4.x, a0);
        a1 = fmaf(src[(size_t)(ic + 1) * stride + p], w4.y, a1);
        a2 = fmaf(src[(size_t)(ic + 2) * stride + p], w4.z, a2);
        a3 = fmaf(src[(size_t)(ic + 3) * stride + p], w4.w, a3);
    }
    float acc = bias + ((a0 + a1) + (a2 + a3));
    g_score[n] = acc;
    out[OFF_SCORE + n] = acc;
}

// ================= greedy NMS ==============================================
__global__ void nms_kernel(const int* __restrict__ anchors, float* __restrict__ out)
{
    int b = blockIdx.x, tid = threadIdx.x;
    __shared__ float s[NA];
    __shared__ float rv[256];
    __shared__ int   ri[256];
    __shared__ float pbox[4];
    __shared__ float parea;

    for (int j = tid; j < NA; j += 256) s[j] = g_score[b * NA + j];
    __syncthreads();

    for (int k = 0; k < TOPN; k++) {
        float bv = neg_inf(); int bi = 0x7fffffff;
        for (int j = tid; j < NA; j += 256) {
            float v = s[j];
            if (v > bv || (v == bv && j < bi)) { bv = v; bi = j; }
        }
        rv[tid] = bv; ri[tid] = bi;
        __syncthreads();
        for (int st = 128; st > 0; st >>= 1) {
            if (tid < st) {
                float v2 = rv[tid + st]; int i2 = ri[tid + st];
                if (v2 > rv[tid] || (v2 == rv[tid] && i2 < ri[tid])) {
                    rv[tid] = v2; ri[tid] = i2;
                }
            }
            __syncthreads();
        }
        if (tid == 0) {
            int pick = ri[0];
            const int* a = anchors + (size_t)pick * 4;
            pbox[0] = (float)a[0]; pbox[1] = (float)a[1];
            pbox[2] = (float)a[2]; pbox[3] = (float)a[3];
            parea = (pbox[2] - pbox[0]) * (pbox[3] - pbox[1]);
            g_topidx[b * TOPN + k] = pick;
            out[OFF_TIDX  + b * TOPN + k] = (float)pick;
            out[OFF_TPROB + b * TOPN + k] = rv[0];
        }
        __syncthreads();
        float y0 = pbox[0], x0 = pbox[1], y1 = pbox[2], x1 = pbox[3], pa = parea;
        for (int j = tid; j < NA; j += 256) {
            const int* a = anchors + (size_t)j * 4;
            float ay0 = (float)a[0], ax0 = (float)a[1];
            float ay1 = (float)a[2], ax1 = (float)a[3];
            float iy = fmaxf(fminf(ay1, y1) - fmaxf(ay0, y0), 0.f);
            float ix = fmaxf(fminf(ax1, x1) - fmaxf(ax0, x0), 0.f);
            float inter = iy * ix;
            float area  = (ay1 - ay0) * (ax1 - ax0);
            float iou = inter / (area + pa - inter);
            if (iou >= 0.25f) s[j] = neg_inf();
        }
        __syncthreads();
    }
}

// ================= crop + bilinear resize =================================
__device__ __forceinline__ float fetchpix(const float* __restrict__ xb, int yy, int xx)
{
    yy -= PAD_S; xx -= PAD_S;
    if ((unsigned)yy < (unsigned)IM_S && (unsigned)xx < (unsigned)IM_S)
        return __ldg(&xb[(size_t)yy * IM_S + xx]);
    return 0.f;
}

__global__ void crop_kernel(const float* __restrict__ x,
                            const int* __restrict__ anchors,
                            float* __restrict__ out)
{
    const int crop = blockIdx.x;
    const int oy   = blockIdx.y;
    const int ox   = threadIdx.x;
    const int b    = crop >> 2;

    const int pick = g_topidx[crop];
    const int* a = anchors + (size_t)pick * 4;
    float y0 = (float)a[0], x0 = (float)a[1], y1 = (float)a[2], x1 = (float)a[3];

    float ty = (float)oy / 223.0f;
    float tx = (float)ox / 223.0f;
    float ys = y0 + ty * (y1 - y0 - 1.0f);
    float xs = x0 + tx * (x1 - x0 - 1.0f);
    int yi0 = (int)floorf(ys); int yi1 = min(yi0 + 1, HP_S - 1);
    int xi0 = (int)floorf(xs); int xi1 = min(xi0 + 1, HP_S - 1);
    float wy = ys - (float)yi0;
    float wx = xs - (float)xi0;
    float c00 = (1.f - wy) * (1.f - wx);
    float c01 = (1.f - wy) * wx;
    float c10 = wy * (1.f - wx);
    float c11 = wy * wx;

#pragma unroll
    for (int c = 0; c < 3; c++) {
        const float* xb = x + ((size_t)b * 3 + c) * IM_S * IM_S;
        float v = fetchpix(xb, yi0, xi0) * c00
                + fetchpix(xb, yi0, xi1) * c01
                + fetchpix(xb, yi1, xi0) * c10
                + fetchpix(xb, yi1, xi1) * c11;
        out[(((size_t)crop * 3 + c) * OUT_S + oy) * OUT_S + ox] = v;
    }
}

// =========================================================================
extern "C" void kernel_launch(void* const* d_in, const int* in_sizes, int n_in,
                              void* d_out, int out_size)
{
    const float* x    = (const float*)d_in[0];
    const float* rpn  = (const float*)d_in[1];
    const float* w1   = (const float*)d_in[2];
    const float* b1   = (const float*)d_in[3];
    const float* w2   = (const float*)d_in[4];
    const float* b2   = (const float*)d_in[5];
    const float* w3   = (const float*)d_in[6];
    const float* b3   = (const float*)d_in[7];
    const float* wt1  = (const float*)d_in[8];
    const float* bt1  = (const float*)d_in[9];
    const float* wt2  = (const float*)d_in[10];
    const float* bt2  = (const float*)d_in[11];
    const float* wt3  = (const float*)d_in[12];
    const float* bt3  = (const float*)d_in[13];
    const int*   anc  = (const int*)d_in[14];
    float* out = (float*)d_out;

    cudaFuncSetAttribute(conv1_mma, cudaFuncAttributeMaxDynamicSharedMemorySize, SM_TOT);

    prep_w<<<(128 * 2048 + 255) / 256, 256>>>(w1);
    prep_in<<<dim3(64, BATCH), 256>>>(rpn);
    dummy_kernel<<<1, 32>>>();   // keeps conv1_mma in ncu's 4th-launch capture slot

    conv1_mma<<<dim3(KSPLIT, BATCH), 256, SM_TOT>>>();
    finalize1_kernel<<<(NP1 + 255) / 256, 256>>>(b1);
    conv2_kernel<<<dim3((N2 + 255) / 256, KS2), 256>>>(w2);
    reduce2_kernel<<<(N2 + 255) / 256, 256>>>(b2);
    conv3_kernel<<<dim3((N3 + 255) / 256, KS3), 256>>>(w3);
    reduce3_kernel<<<(N3 + 255) / 256, 256>>>(b3);
    tidy_kernel<<<(BATCH * NA + 255) / 256, 256>>>(wt1, bt1, wt2, bt2, wt3, bt3, out);
    nms_kernel<<<BATCH, 256>>>(anc, out);
    crop_kernel<<<dim3(BATCH * TOPN, OUT_S), OUT_S>>>(x, anc, out);
}

// round 10
// speedup vs baseline: 4.8302x; 1.2271x over previous
#include <cuda_runtime.h>
#include <cuda_bf16.h>
#include <math.h>
#include <stdint.h>

// ---------------- problem constants ----------------
#define BATCH   16
#define TOPN    4
#define NA      1614
#define OUT_S   224
#define IM_S    448
#define PAD_S   224
#define HP_S    896

#define NPART   (BATCH*TOPN*3*OUT_S*OUT_S)   // 9,633,792
#define OFF_TIDX  NPART
#define OFF_TPROB (NPART + BATCH*TOPN)
#define OFF_SCORE (NPART + 2*BATCH*TOPN)

// conv1: K split tap-major -- one tap (of 9) per CTA-column, K=2048 ic each
#define KSPLIT  9
#define NCHUNK  32                 // 2048 ic / 64 per chunk
#define NP1     (BATCH*128*196)    // 401,408

#define N2      (BATCH*128*49)     // 100,352
#define N3      (BATCH*128*16)     // 32,768

// ---------------- scratch ----------------
__device__ float g_part1[(size_t)KSPLIT * NP1];
__device__ float g_d1[NP1];
__device__ float g_p2[(size_t)9 * N2];
__device__ float g_d2[N2];
__device__ float g_p3[(size_t)9 * N3];
__device__ float g_d3[N3];
__device__ float g_score[BATCH*NA];
__device__ int   g_topidx[BATCH*TOPN];

// bf16 hi/lo prepped operands
__device__ __nv_bfloat16 g_wh[(size_t)9 * 128 * 2048];     // conv1 w [tap][oc][ic]
__device__ __nv_bfloat16 g_wl[(size_t)9 * 128 * 2048];
__device__ __nv_bfloat16 g_ih[(size_t)BATCH * 288 * 2048]; // conv1 in [b][pos 16x18][ic]
__device__ __nv_bfloat16 g_il[(size_t)BATCH * 288 * 2048];
__device__ __nv_bfloat16 g_w2h[(size_t)9 * 128 * 128];     // conv2 w [tap][oc][ic]
__device__ __nv_bfloat16 g_w2l[(size_t)9 * 128 * 128];
__device__ __nv_bfloat16 g_w3h[(size_t)9 * 128 * 128];
__device__ __nv_bfloat16 g_w3l[(size_t)9 * 128 * 128];
__device__ __nv_bfloat16 g_d1h[(size_t)BATCH * 256 * 128]; // d1 planes [b][pos 16x16][ic]
__device__ __nv_bfloat16 g_d1l[(size_t)BATCH * 256 * 128];
__device__ __nv_bfloat16 g_d2h[(size_t)BATCH * 256 * 128]; // d2 planes
__device__ __nv_bfloat16 g_d2l[(size_t)BATCH * 256 * 128];

__device__ __forceinline__ float neg_inf() { return __int_as_float(0xff800000); }

__device__ __forceinline__ uint32_t smem_to_u32(const void* p) {
    uint32_t a;
    asm("{ .reg .u64 t; cvta.to.shared.u64 t, %1; cvt.u32.u64 %0, t; }"
        : "=r"(a) : "l"(p));
    return a;
}
__device__ __forceinline__ void cpa16(uint32_t dst, const void* src) {
    asm volatile("cp.async.cg.shared.global [%0], [%1], 16;"
                 :: "r"(dst), "l"(src) : "memory");
}
__device__ __forceinline__ void ldsm_x4(uint32_t& r0, uint32_t& r1, uint32_t& r2, uint32_t& r3,
                                        uint32_t addr) {
    asm volatile("ldmatrix.sync.aligned.m8n8.x4.shared.b16 {%0,%1,%2,%3}, [%4];"
                 : "=r"(r0), "=r"(r1), "=r"(r2), "=r"(r3) : "r"(addr));
}
__device__ __forceinline__ void ldsm_x2(uint32_t& r0, uint32_t& r1, uint32_t addr) {
    asm volatile("ldmatrix.sync.aligned.m8n8.x2.shared.b16 {%0,%1}, [%2];"
                 : "=r"(r0), "=r"(r1) : "r"(addr));
}
__device__ __forceinline__ void mma16816(float* c, uint32_t a0, uint32_t a1, uint32_t a2,
                                         uint32_t a3, uint32_t b0, uint32_t b1) {
    asm volatile("mma.sync.aligned.m16n8k16.row.col.f32.bf16.bf16.f32 "
                 "{%0,%1,%2,%3}, {%4,%5,%6,%7}, {%8,%9}, {%0,%1,%2,%3};"
                 : "+f"(c[0]), "+f"(c[1]), "+f"(c[2]), "+f"(c[3])
                 : "r"(a0), "r"(a1), "r"(a2), "r"(a3), "r"(b0), "r"(b1));
}
__device__ __forceinline__ void bfsplit(float v, __nv_bfloat16& h, __nv_bfloat16& l) {
    h = __float2bfloat16_rn(v);
    l = __float2bfloat16_rn(v - __bfloat162float(h));
}
__device__ __forceinline__ uint32_t pkbf(__nv_bfloat16 a, __nv_bfloat16 b) {
    return (uint32_t)__bfloat16_as_ushort(a) | ((uint32_t)__bfloat16_as_ushort(b) << 16);
}

// ================= prep_w1: conv1 weights -> bf16 hi/lo tap-major ========
__global__ void prep_w1(const float* __restrict__ w)
{
    int idx = blockIdx.x * 256 + threadIdx.x;
    if (idx >= 128 * 2048) return;
    int oc = idx >> 11, ic = idx & 2047;
    const float* src = w + (size_t)oc * 18432 + (size_t)ic * 9;
#pragma unroll
    for (int t = 0; t < 9; t++) {
        __nv_bfloat16 h, l;
        bfsplit(__ldg(&src[t]), h, l);
        size_t d = ((size_t)t * 128 + oc) * 2048 + ic;
        g_wh[d] = h; g_wl[d] = l;
    }
}

// ================= prep_w23: conv2/conv3 weights -> bf16 hi/lo tap-major ==
__global__ void prep_w23(const float* __restrict__ w2, const float* __restrict__ w3)
{
    int idx = blockIdx.x * 256 + threadIdx.x;
    if (idx >= 2 * 128 * 128) return;
    int which = idx >> 14, r = idx & 16383;
    int oc = r >> 7, ic = r & 127;
    const float* src = (which ? w3 : w2) + (size_t)(oc * 128 + ic) * 9;
    __nv_bfloat16* dh = which ? g_w3h : g_w2h;
    __nv_bfloat16* dl = which ? g_w3l : g_w2l;
#pragma unroll
    for (int t = 0; t < 9; t++) {
        __nv_bfloat16 h, l;
        bfsplit(__ldg(&src[t]), h, l);
        size_t d = ((size_t)t * 128 + oc) * 128 + ic;
        dh[d] = h; dl[d] = l;
    }
}

// ================= prep_in: rpn -> bf16 hi/lo transposed padded planes ====
__global__ void prep_in(const float* __restrict__ in)
{
    __shared__ float s_in[32][197];
    const int icb = blockIdx.x;          // 0..63 (32 ic each)
    const int b   = blockIdx.y;
    const int tid = threadIdx.x;

    const float* src = in + ((size_t)b * 2048 + icb * 32) * 196;
    for (int i = tid; i < 32 * 196; i += 256)
        s_in[i / 196][i % 196] = __ldg(&src[i]);
    __syncthreads();

    for (int i = tid; i < 288 * 16; i += 256) {
        int pos = i >> 4, icp = i & 15;
        int py = pos / 18, px = pos % 18;
        int iy = py - 1, ix = px - 1;
        float v0 = 0.f, v1 = 0.f;
        if ((unsigned)iy < 14u && (unsigned)ix < 14u) {
            v0 = s_in[icp * 2][iy * 14 + ix];
            v1 = s_in[icp * 2 + 1][iy * 14 + ix];
        }
        __nv_bfloat16 h0, l0, h1, l1;
        bfsplit(v0, h0, l0); bfsplit(v1, h1, l1);
        size_t d = ((size_t)b * 288 + pos) * 2048 + icb * 32 + icp * 2;
        *(uint32_t*)&g_ih[d] = pkbf(h0, h1);
        *(uint32_t*)&g_il[d] = pkbf(l0, l1);
    }
}

// ================= conv1 via mma.sync, cp.async double-buffered ===========
#define SA_H   0
#define SA_L   18432
#define SB_H   36864
#define SB_L   69120
#define STG_SZ 101376
#define SM_TOT (2 * STG_SZ)

__global__ void __launch_bounds__(256) conv1_mma()
{
    extern __shared__ __align__(16) char smem[];
    const uint32_t sb = smem_to_u32(smem);
    const int tid = threadIdx.x, wid = tid >> 5, lane = tid & 31;
    const int t = blockIdx.x, b = blockIdx.y;
    const int dy = t / 3 - 1, dx = t % 3 - 1;

    const int mrow = wid & 3;
    const int ncol = wid >> 2;

    float acc[2][14][4];
#pragma unroll
    for (int mt = 0; mt < 2; mt++)
#pragma unroll
        for (int nt = 0; nt < 14; nt++)
#pragma unroll
            for (int i = 0; i < 4; i++) acc[mt][nt][i] = 0.f;

    const __nv_bfloat16* ah0 = g_wh + ((size_t)t * 128) * 2048;
    const __nv_bfloat16* al0 = g_wl + ((size_t)t * 128) * 2048;
    const __nv_bfloat16* bh0 = g_ih + (size_t)b * 288 * 2048;
    const __nv_bfloat16* bl0 = g_il + (size_t)b * 288 * 2048;

    auto fill = [&](int stage, int c) {
        const uint32_t s0 = sb + stage * STG_SZ;
        const int kof = c * 64;
        for (int idx = tid; idx < 1024; idx += 256) {
            int row = idx >> 3, seg = idx & 7;
            uint32_t off = (uint32_t)(row * 144 + seg * 16);
            size_t so = (size_t)row * 2048 + kof + seg * 8;
            cpa16(s0 + SA_H + off, ah0 + so);
            cpa16(s0 + SA_L + off, al0 + so);
        }
        for (int idx = tid; idx < 1792; idx += 256) {
            int row = idx >> 3, seg = idx & 7;
            int y = row >> 4, x = row & 15;
            int pos = (y + dy + 1) * 18 + (x + dx + 1);
            uint32_t off = (uint32_t)(row * 144 + seg * 16);
            size_t so = (size_t)pos * 2048 + kof + seg * 8;
            cpa16(s0 + SB_H + off, bh0 + so);
            cpa16(s0 + SB_L + off, bl0 + so);
        }
        asm volatile("cp.async.commit_group;" ::: "memory");
    };

    const uint32_t aRow = (uint32_t)(lane & 15);
    const uint32_t aHalf = (uint32_t)(lane >> 4) * 16;
    const uint32_t bRow = (uint32_t)(lane & 7);
    const uint32_t bHalf = (uint32_t)((lane >> 3) & 1) * 16;

    fill(0, 0);
    int s = 0;
    for (int c = 0; c < NCHUNK; c++) {
        if (c + 1 < NCHUNK) {
            fill(s ^ 1, c + 1);
            asm volatile("cp.async.wait_group 1;" ::: "memory");
        } else {
            asm volatile("cp.async.wait_group 0;" ::: "memory");
        }
        __syncthreads();

        const uint32_t s0 = sb + s * STG_SZ;
#pragma unroll
        for (int kkstep = 0; kkstep < 4; kkstep++) {
            const uint32_t kb = (uint32_t)kkstep * 32;
            uint32_t ah[2][4], al[2][4];
#pragma unroll
            for (int mt = 0; mt < 2; mt++) {
                uint32_t ra = (uint32_t)((mrow * 32 + mt * 16 + aRow) * 144) + kb + aHalf;
                ldsm_x4(ah[mt][0], ah[mt][1], ah[mt][2], ah[mt][3], s0 + SA_H + ra);
                ldsm_x4(al[mt][0], al[mt][1], al[mt][2], al[mt][3], s0 + SA_L + ra);
            }
            // B fragment double buffer: load nt+1 while issuing MMAs on nt
            uint32_t bh[2][2], bl[2][2];
            {
                uint32_t rb = (uint32_t)((ncol * 112 + bRow) * 144) + kb + bHalf;
                ldsm_x2(bh[0][0], bh[0][1], s0 + SB_H + rb);
                ldsm_x2(bl[0][0], bl[0][1], s0 + SB_L + rb);
            }
#pragma unroll
            for (int nt = 0; nt < 14; nt++) {
                const int cur = nt & 1;
                if (nt < 13) {
                    uint32_t rb = (uint32_t)((ncol * 112 + (nt + 1) * 8 + bRow) * 144) + kb + bHalf;
                    ldsm_x2(bh[cur ^ 1][0], bh[cur ^ 1][1], s0 + SB_H + rb);
                    ldsm_x2(bl[cur ^ 1][0], bl[cur ^ 1][1], s0 + SB_L + rb);
                }
#pragma unroll
                for (int mt = 0; mt < 2; mt++) {
                    mma16816(acc[mt][nt], ah[mt][0], ah[mt][1], ah[mt][2], ah[mt][3], bh[cur][0], bh[cur][1]);
                    mma16816(acc[mt][nt], ah[mt][0], ah[mt][1], ah[mt][2], ah[mt][3], bl[cur][0], bl[cur][1]);
                    mma16816(acc[mt][nt], al[mt][0], al[mt][1], al[mt][2], al[mt][3], bh[cur][0], bh[cur][1]);
                }
            }
        }
        __syncthreads();
        s ^= 1;
    }

    const int r = lane >> 2, q = lane & 3;
    float* pp = g_part1 + (size_t)t * NP1 + ((size_t)b * 128) * 196;
#pragma unroll
    for (int mt = 0; mt < 2; mt++) {
        int oc0 = mrow * 32 + mt * 16 + r;
#pragma unroll
        for (int nt = 0; nt < 14; nt++) {
            int n0 = ncol * 112 + nt * 8 + 2 * q;
            int y0 = n0 >> 4, x0 = n0 & 15;
            int y1 = (n0 + 1) >> 4, x1 = (n0 + 1) & 15;
            if (x0 < 14) {
                pp[(size_t)oc0 * 196 + y0 * 14 + x0]       = acc[mt][nt][0];
                pp[(size_t)(oc0 + 8) * 196 + y0 * 14 + x0] = acc[mt][nt][2];
            }
            if (x1 < 14) {
                pp[(size_t)oc0 * 196 + y1 * 14 + x1]       = acc[mt][nt][1];
                pp[(size_t)(oc0 + 8) * 196 + y1 * 14 + x1] = acc[mt][nt][3];
            }
        }
    }
}

// deterministic split-K reduce + bias + relu
__global__ void finalize1_kernel(const float* __restrict__ bias)
{
    int n = blockIdx.x * 256 + threadIdx.x;
    if (n >= NP1) return;
    float s = 0.f;
#pragma unroll
    for (int k = 0; k < KSPLIT; k++) s += g_part1[(size_t)k * NP1 + n];
    int oc = (n / 196) & 127;
    g_d1[n] = fmaxf(s + __ldg(&bias[oc]), 0.f);
}

// ================= pack_planes: f32 [b][128][P] -> bf16 hi/lo [b][256][128]
// pos = py*16+px, source (py-1, px-1) valid in WxW else zero.
__global__ void pack_planes(const float* __restrict__ src,
                            __nv_bfloat16* __restrict__ dsth,
                            __nv_bfloat16* __restrict__ dstl,
                            int W, int P)
{
    __shared__ float s_in[32][197];
    const int icb = blockIdx.x;          // 0..3 (32 ic each)
    const int b   = blockIdx.y;
    const int tid = threadIdx.x;

    const float* sp = src + ((size_t)b * 128 + icb * 32) * P;
    for (int i = tid; i < 32 * P; i += 256)
        s_in[i / P][i % P] = sp[i];
    __syncthreads();

    for (int i = tid; i < 256 * 16; i += 256) {
        int pos = i >> 4, icp = i & 15;
        int py = pos >> 4, px = pos & 15;
        int iy = py - 1, ix = px - 1;
        float v0 = 0.f, v1 = 0.f;
        if ((unsigned)iy < (unsigned)W && (unsigned)ix < (unsigned)W) {
            v0 = s_in[icp * 2][iy * W + ix];
            v1 = s_in[icp * 2 + 1][iy * W + ix];
        }
        __nv_bfloat16 h0, l0, h1, l1;
        bfsplit(v0, h0, l0); bfsplit(v1, h1, l1);
        size_t d = ((size_t)b * 256 + pos) * 128 + icb * 32 + icp * 2;
        *(uint32_t*)&dsth[d] = pkbf(h0, h1);
        *(uint32_t*)&dstl[d] = pkbf(l0, l1);
    }
}

// ================= conv23_mma: stride-2 3x3 conv, M=128, N=64(pad), K=128 =
// grid (9 taps, 16 batches). Partials [tap][b][128 oc][NVALID].
#define C23_A_H  0
#define C23_A_L  34816
#define C23_B_H  69632
#define C23_B_L  87040
#define C23_TOT  104448

__global__ void __launch_bounds__(256) conv23_mma(const __nv_bfloat16* __restrict__ wh,
                                                  const __nv_bfloat16* __restrict__ wl,
                                                  const __nv_bfloat16* __restrict__ inh,
                                                  const __nv_bfloat16* __restrict__ inl,
                                                  float* __restrict__ part,
                                                  int OW, int NVALID)
{
    extern __shared__ __align__(16) char smem[];
    const uint32_t sb = smem_to_u32(smem);
    const int tid = threadIdx.x, wid = tid >> 5, lane = tid & 31;
    const int t = blockIdx.x, b = blockIdx.y;
    const int dy = t / 3 - 1, dx = t % 3 - 1;
    const int mrow = wid & 3;    // oc 32-block
    const int ncol = wid >> 2;   // n 32-block (of 64)

    const __nv_bfloat16* ah0 = wh + (size_t)t * 128 * 128;
    const __nv_bfloat16* al0 = wl + (size_t)t * 128 * 128;
    const __nv_bfloat16* bh0 = inh + (size_t)b * 256 * 128;
    const __nv_bfloat16* bl0 = inl + (size_t)b * 256 * 128;

    // fill A: 128 rows x 16 segs, pitch 272
    for (int idx = tid; idx < 2048; idx += 256) {
        int row = idx >> 4, seg = idx & 15;
        uint32_t off = (uint32_t)(row * 272 + seg * 16);
        size_t so = (size_t)row * 128 + seg * 8;
        cpa16(sb + C23_A_H + off, ah0 + so);
        cpa16(sb + C23_A_L + off, al0 + so);
    }
    // fill B: 64 rows (junk beyond NVALID) x 16 segs
    for (int idx = tid; idx < 1024; idx += 256) {
        int row = idx >> 4, seg = idx & 15;
        int pos = 0;
        if (row < NVALID) {
            int oy = row / OW, ox = row % OW;
            pos = (2 * oy + dy + 1) * 16 + (2 * ox + dx + 1);
        }
        uint32_t off = (uint32_t)(row * 272 + seg * 16);
        size_t so = (size_t)pos * 128 + seg * 8;
        cpa16(sb + C23_B_H + off, bh0 + so);
        cpa16(sb + C23_B_L + off, bl0 + so);
    }
    asm volatile("cp.async.commit_group;" ::: "memory");
    asm volatile("cp.async.wait_group 0;" ::: "memory");
    __syncthreads();

    float acc[2][4][4];
#pragma unroll
    for (int mt = 0; mt < 2; mt++)
#pragma unroll
        for (int nt = 0; nt < 4; nt++)
#pragma unroll
            for (int i = 0; i < 4; i++) acc[mt][nt][i] = 0.f;

    const uint32_t aRow = (uint32_t)(lane & 15);
    const uint32_t aHalf = (uint32_t)(lane >> 4) * 16;
    const uint32_t bRow = (uint32_t)(lane & 7);
    const uint32_t bHalf = (uint32_t)((lane >> 3) & 1) * 16;

#pragma unroll
    for (int kkstep = 0; kkstep < 8; kkstep++) {
        const uint32_t kb = (uint32_t)kkstep * 32;
        uint32_t ah[2][4], al[2][4];
#pragma unroll
        for (int mt = 0; mt < 2; mt++) {
            uint32_t ra = (uint32_t)((mrow * 32 + mt * 16 + aRow) * 272) + kb + aHalf;
            ldsm_x4(ah[mt][0], ah[mt][1], ah[mt][2], ah[mt][3], sb + C23_A_H + ra);
            ldsm_x4(al[mt][0], al[mt][1], al[mt][2], al[mt][3], sb + C23_A_L + ra);
        }
#pragma unroll
        for (int nt = 0; nt < 4; nt++) {
            uint32_t rb = (uint32_t)((ncol * 32 + nt * 8 + bRow) * 272) + kb + bHalf;
            uint32_t bhr0, bhr1, blr0, blr1;
            ldsm_x2(bhr0, bhr1, sb + C23_B_H + rb);
            ldsm_x2(blr0, blr1, sb + C23_B_L + rb);
#pragma unroll
            for (int mt = 0; mt < 2; mt++) {
                mma16816(acc[mt][nt], ah[mt][0], ah[mt][1], ah[mt][2], ah[mt][3], bhr0, bhr1);
                mma16816(acc[mt][nt], ah[mt][0], ah[mt][1], ah[mt][2], ah[mt][3], blr0, blr1);
                mma16816(acc[mt][nt], al[mt][0], al[mt][1], al[mt][2], al[mt][3], bhr0, bhr1);
            }
        }
    }

    const int r = lane >> 2, q = lane & 3;
    float* pp = part + ((size_t)t * BATCH + b) * 128 * NVALID;
#pragma unroll
    for (int mt = 0; mt < 2; mt++) {
        int oc0 = mrow * 32 + mt * 16 + r;
#pragma unroll
        for (int nt = 0; nt < 4; nt++) {
            int n0 = ncol * 32 + nt * 8 + 2 * q;
            if (n0 < NVALID) {
                pp[(size_t)oc0 * NVALID + n0]       = acc[mt][nt][0];
                pp[(size_t)(oc0 + 8) * NVALID + n0] = acc[mt][nt][2];
            }
            if (n0 + 1 < NVALID) {
                pp[(size_t)oc0 * NVALID + n0 + 1]       = acc[mt][nt][1];
                pp[(size_t)(oc0 + 8) * NVALID + n0 + 1] = acc[mt][nt][3];
            }
        }
    }
}

__global__ void reduce2_kernel(const float* __restrict__ bias)
{
    int n = blockIdx.x * 256 + threadIdx.x;
    if (n >= N2) return;
    float s = __ldg(&bias[(n / 49) & 127]);
#pragma unroll
    for (int k = 0; k < 9; k++) s += g_p2[(size_t)k * N2 + n];
    g_d2[n] = fmaxf(s, 0.f);
}

__global__ void reduce3_kernel(const float* __restrict__ bias)
{
    int n = blockIdx.x * 256 + threadIdx.x;
    if (n >= N3) return;
    float s = __ldg(&bias[(n / 16) & 127]);
#pragma unroll
    for (int k = 0; k < 9; k++) s += g_p3[(size_t)k * N3 + n];
    g_d3[n] = fmaxf(s, 0.f);
}

// ================= tidy 1x1 convs -> concatenated scores =================
__global__ void tidy_kernel(const float* __restrict__ wt1, const float* __restrict__ bt1,
                            const float* __restrict__ wt2, const float* __restrict__ bt2,
                            const float* __restrict__ wt3, const float* __restrict__ bt3,
                            float* __restrict__ out)
{
    int n = blockIdx.x * 256 + threadIdx.x;
    if (n >= BATCH * NA) return;
    int b = n / NA, j = n % NA;
    const float* src; const float* wt; float bias; int c, p, stride;
    if (j < 1176) {
        c = j / 196; p = j % 196;
        src = g_d1 + (size_t)b * 128 * 196; stride = 196;
        wt = wt1; bias = __ldg(&bt1[c]);
    } else if (j < 1470) {
        int jj = j - 1176; c = jj / 49; p = jj % 49;
        src = g_d2 + (size_t)b * 128 * 49; stride = 49;
        wt = wt2; bias = __ldg(&bt2[c]);
    } else {
        int jj = j - 1470; c = jj / 16; p = jj % 16;
        src = g_d3 + (size_t)b * 128 * 16; stride = 16;
        wt = wt3; bias = __ldg(&bt3[c]);
    }
    const float4* wv = (const float4*)(wt + (size_t)c * 128);
    float a0 = 0.f, a1 = 0.f, a2 = 0.f, a3 = 0.f;
#pragma unroll 8
    for (int i = 0; i < 32; i++) {
        float4 w4 = __ldg(&wv[i]);
        int ic = 4 * i;
        a0 = fmaf(src[(size_t)(ic + 0) * stride + p], w4.x, a0);
        a1 = fmaf(src[(size_t)(ic + 1) * stride + p], w4.y, a1);
        a2 = fmaf(src[(size_t)(ic + 2) * stride + p], w4.z, a2);
        a3 = fmaf(src[(size_t)(ic + 3) * stride + p], w4.w, a3);
    }
    float acc = bias + ((a0 + a1) + (a2 + a3));
    g_score[n] = acc;
    out[OFF_SCORE + n] = acc;
}

// ================= greedy NMS ==============================================
__global__ void nms_kernel(const int* __restrict__ anchors, float* __restrict__ out)
{
    int b = blockIdx.x, tid = threadIdx.x;
    __shared__ float s[NA];
    __shared__ float rv[256];
    __shared__ int   ri[256];
    __shared__ float pbox[4];
    __shared__ float parea;

    for (int j = tid; j < NA; j += 256) s[j] = g_score[b * NA + j];
    __syncthreads();

    for (int k = 0; k < TOPN; k++) {
        float bv = neg_inf(); int bi = 0x7fffffff;
        for (int j = tid; j < NA; j += 256) {
            float v = s[j];
            if (v > bv || (v == bv && j < bi)) { bv = v; bi = j; }
        }
        rv[tid] = bv; ri[tid] = bi;
        __syncthreads();
        for (int st = 128; st > 0; st >>= 1) {
            if (tid < st) {
                float v2 = rv[tid + st]; int i2 = ri[tid + st];
                if (v2 > rv[tid] || (v2 == rv[tid] && i2 < ri[tid])) {
                    rv[tid] = v2; ri[tid] = i2;
                }
            }
            __syncthreads();
        }
        if (tid == 0) {
            int pick = ri[0];
            const int* a = anchors + (size_t)pick * 4;
            pbox[0] = (float)a[0]; pbox[1] = (float)a[1];
            pbox[2] = (float)a[2]; pbox[3] = (float)a[3];
            parea = (pbox[2] - pbox[0]) * (pbox[3] - pbox[1]);
            g_topidx[b * TOPN + k] = pick;
            out[OFF_TIDX  + b * TOPN + k] = (float)pick;
            out[OFF_TPROB + b * TOPN + k] = rv[0];
        }
        __syncthreads();
        float y0 = pbox[0], x0 = pbox[1], y1 = pbox[2], x1 = pbox[3], pa = parea;
        for (int j = tid; j < NA; j += 256) {
            const int* a = anchors + (size_t)j * 4;
            float ay0 = (float)a[0], ax0 = (float)a[1];
            float ay1 = (float)a[2], ax1 = (float)a[3];
            float iy = fmaxf(fminf(ay1, y1) - fmaxf(ay0, y0), 0.f);
            float ix = fmaxf(fminf(ax1, x1) - fmaxf(ax0, x0), 0.f);
            float inter = iy * ix;
            float area  = (ay1 - ay0) * (ax1 - ax0);
            float iou = inter / (area + pa - inter);
            if (iou >= 0.25f) s[j] = neg_inf();
        }
        __syncthreads();
    }
}

// ================= crop + bilinear resize =================================
__device__ __forceinline__ float fetchpix(const float* __restrict__ xb, int yy, int xx)
{
    yy -= PAD_S; xx -= PAD_S;
    if ((unsigned)yy < (unsigned)IM_S && (unsigned)xx < (unsigned)IM_S)
        return __ldg(&xb[(size_t)yy * IM_S + xx]);
    return 0.f;
}

__global__ void crop_kernel(const float* __restrict__ x,
                            const int* __restrict__ anchors,
                            float* __restrict__ out)
{
    const int crop = blockIdx.x;
    const int oy   = blockIdx.y;
    const int ox   = threadIdx.x;
    const int b    = crop >> 2;

    const int pick = g_topidx[crop];
    const int* a = anchors + (size_t)pick * 4;
    float y0 = (float)a[0], x0 = (float)a[1], y1 = (float)a[2], x1 = (float)a[3];

    float ty = (float)oy / 223.0f;
    float tx = (float)ox / 223.0f;
    float ys = y0 + ty * (y1 - y0 - 1.0f);
    float xs = x0 + tx * (x1 - x0 - 1.0f);
    int yi0 = (int)floorf(ys); int yi1 = min(yi0 + 1, HP_S - 1);
    int xi0 = (int)floorf(xs); int xi1 = min(xi0 + 1, HP_S - 1);
    float wy = ys - (float)yi0;
    float wx = xs - (float)xi0;
    float c00 = (1.f - wy) * (1.f - wx);
    float c01 = (1.f - wy) * wx;
    float c10 = wy * (1.f - wx);
    float c11 = wy * wx;

#pragma unroll
    for (int c = 0; c < 3; c++) {
        const float* xb = x + ((size_t)b * 3 + c) * IM_S * IM_S;
        float v = fetchpix(xb, yi0, xi0) * c00
                + fetchpix(xb, yi0, xi1) * c01
                + fetchpix(xb, yi1, xi0) * c10
                + fetchpix(xb, yi1, xi1) * c11;
        out[(((size_t)crop * 3 + c) * OUT_S + oy) * OUT_S + ox] = v;
    }
}

// =========================================================================
extern "C" void kernel_launch(void* const* d_in, const int* in_sizes, int n_in,
                              void* d_out, int out_size)
{
    const float* x    = (const float*)d_in[0];
    const float* rpn  = (const float*)d_in[1];
    const float* w1   = (const float*)d_in[2];
    const float* b1   = (const float*)d_in[3];
    const float* w2   = (const float*)d_in[4];
    const float* b2   = (const float*)d_in[5];
    const float* w3   = (const float*)d_in[6];
    const float* b3   = (const float*)d_in[7];
    const float* wt1  = (const float*)d_in[8];
    const float* bt1  = (const float*)d_in[9];
    const float* wt2  = (const float*)d_in[10];
    const float* bt2  = (const float*)d_in[11];
    const float* wt3  = (const float*)d_in[12];
    const float* bt3  = (const float*)d_in[13];
    const int*   anc  = (const int*)d_in[14];
    float* out = (float*)d_out;

    cudaFuncSetAttribute(conv1_mma, cudaFuncAttributeMaxDynamicSharedMemorySize, SM_TOT);
    cudaFuncSetAttribute(conv23_mma, cudaFuncAttributeMaxDynamicSharedMemorySize, C23_TOT);

    float *p2, *p3;
    cudaGetSymbolAddress((void**)&p2, g_p2);
    cudaGetSymbolAddress((void**)&p3, g_p3);
    __nv_bfloat16 *w2h, *w2l, *w3h, *w3l, *d1h, *d1l, *d2h, *d2l;
    cudaGetSymbolAddress((void**)&w2h, g_w2h);
    cudaGetSymbolAddress((void**)&w2l, g_w2l);
    cudaGetSymbolAddress((void**)&w3h, g_w3h);
    cudaGetSymbolAddress((void**)&w3l, g_w3l);
    cudaGetSymbolAddress((void**)&d1h, g_d1h);
    cudaGetSymbolAddress((void**)&d1l, g_d1l);
    cudaGetSymbolAddress((void**)&d2h, g_d2h);
    cudaGetSymbolAddress((void**)&d2l, g_d2l);
    float *d1p, *d2p;
    cudaGetSymbolAddress((void**)&d1p, g_d1);
    cudaGetSymbolAddress((void**)&d2p, g_d2);

    prep_w1<<<(128 * 2048 + 255) / 256, 256>>>(w1);
    prep_w23<<<(2 * 128 * 128 + 255) / 256, 256>>>(w2, w3);
    prep_in<<<dim3(64, BATCH), 256>>>(rpn);

    conv1_mma<<<dim3(KSPLIT, BATCH), 256, SM_TOT>>>();   // 4th launch: ncu slot
    finalize1_kernel<<<(NP1 + 255) / 256, 256>>>(b1);

    pack_planes<<<dim3(4, BATCH), 256>>>(d1p, d1h, d1l, 14, 196);
    conv23_mma<<<dim3(9, BATCH), 256, C23_TOT>>>(w2h, w2l, d1h, d1l, p2, 7, 49);
    reduce2_kernel<<<(N2 + 255) / 256, 256>>>(b2);

    pack_planes<<<dim3(4, BATCH), 256>>>(d2p, d2h, d2l, 7, 49);
    conv23_mma<<<dim3(9, BATCH), 256, C23_TOT>>>(w3h, w3l, d2h, d2l, p3, 4, 16);
    reduce3_kernel<<<(N3 + 255) / 256, 256>>>(b3);

    tidy_kernel<<<(BATCH * NA + 255) / 256, 256>>>(wt1, bt1, wt2, bt2, wt3, bt3, out);
    nms_kernel<<<BATCH, 256>>>(anc, out);
    crop_kernel<<<dim3(BATCH * TOPN, OUT_S), OUT_S>>>(x, anc, out);
}

// round 11
// speedup vs baseline: 4.8634x; 1.0069x over previous
#include <cuda_runtime.h>
#include <cuda_bf16.h>
#include <math.h>
#include <stdint.h>

// ---------------- problem constants ----------------
#define BATCH   16
#define TOPN    4
#define NA      1614
#define OUT_S   224
#define IM_S    448
#define PAD_S   224
#define HP_S    896

#define NPART   (BATCH*TOPN*3*OUT_S*OUT_S)   // 9,633,792
#define OFF_TIDX  NPART
#define OFF_TPROB (NPART + BATCH*TOPN)
#define OFF_SCORE (NPART + 2*BATCH*TOPN)

#define KSPLIT  9
#define NCHUNK  32
#define NP1     (BATCH*128*196)

#define N2      (BATCH*128*49)
#define N3      (BATCH*128*16)

// ---------------- scratch ----------------
__device__ float g_part1[(size_t)KSPLIT * NP1];
__device__ float g_d1[NP1];
__device__ float g_p2[(size_t)9 * N2];
__device__ float g_d2[N2];
__device__ float g_p3[(size_t)9 * N3];
__device__ float g_d3[N3];
__device__ float g_score[BATCH*NA];
__device__ int   g_topidx[BATCH*TOPN];

// bf16 hi/lo prepped operands (zero-initialized; plane borders stay zero)
__device__ __nv_bfloat16 g_wh[(size_t)9 * 128 * 2048];
__device__ __nv_bfloat16 g_wl[(size_t)9 * 128 * 2048];
__device__ __nv_bfloat16 g_ih[(size_t)BATCH * 288 * 2048];
__device__ __nv_bfloat16 g_il[(size_t)BATCH * 288 * 2048];
__device__ __nv_bfloat16 g_w2h[(size_t)9 * 128 * 128];
__device__ __nv_bfloat16 g_w2l[(size_t)9 * 128 * 128];
__device__ __nv_bfloat16 g_w3h[(size_t)9 * 128 * 128];
__device__ __nv_bfloat16 g_w3l[(size_t)9 * 128 * 128];
__device__ __nv_bfloat16 g_d1h[(size_t)BATCH * 256 * 128];
__device__ __nv_bfloat16 g_d1l[(size_t)BATCH * 256 * 128];
__device__ __nv_bfloat16 g_d2h[(size_t)BATCH * 256 * 128];
__device__ __nv_bfloat16 g_d2l[(size_t)BATCH * 256 * 128];

__device__ __forceinline__ float neg_inf() { return __int_as_float(0xff800000); }

__device__ __forceinline__ uint32_t smem_to_u32(const void* p) {
    uint32_t a;
    asm("{ .reg .u64 t; cvta.to.shared.u64 t, %1; cvt.u32.u64 %0, t; }"
        : "=r"(a) : "l"(p));
    return a;
}
__device__ __forceinline__ void cpa16(uint32_t dst, const void* src) {
    asm volatile("cp.async.cg.shared.global [%0], [%1], 16;"
                 :: "r"(dst), "l"(src) : "memory");
}
__device__ __forceinline__ void ldsm_x4(uint32_t& r0, uint32_t& r1, uint32_t& r2, uint32_t& r3,
                                        uint32_t addr) {
    asm volatile("ldmatrix.sync.aligned.m8n8.x4.shared.b16 {%0,%1,%2,%3}, [%4];"
                 : "=r"(r0), "=r"(r1), "=r"(r2), "=r"(r3) : "r"(addr));
}
__device__ __forceinline__ void ldsm_x2(uint32_t& r0, uint32_t& r1, uint32_t addr) {
    asm volatile("ldmatrix.sync.aligned.m8n8.x2.shared.b16 {%0,%1}, [%2];"
                 : "=r"(r0), "=r"(r1) : "r"(addr));
}
__device__ __forceinline__ void mma16816(float* c, uint32_t a0, uint32_t a1, uint32_t a2,
                                         uint32_t a3, uint32_t b0, uint32_t b1) {
    asm volatile("mma.sync.aligned.m16n8k16.row.col.f32.bf16.bf16.f32 "
                 "{%0,%1,%2,%3}, {%4,%5,%6,%7}, {%8,%9}, {%0,%1,%2,%3};"
                 : "+f"(c[0]), "+f"(c[1]), "+f"(c[2]), "+f"(c[3])
                 : "r"(a0), "r"(a1), "r"(a2), "r"(a3), "r"(b0), "r"(b1));
}
__device__ __forceinline__ void bfsplit(float v, __nv_bfloat16& h, __nv_bfloat16& l) {
    h = __float2bfloat16_rn(v);
    l = __float2bfloat16_rn(v - __bfloat162float(h));
}
__device__ __forceinline__ uint32_t pkbf(__nv_bfloat16 a, __nv_bfloat16 b) {
    return (uint32_t)__bfloat16_as_ushort(a) | ((uint32_t)__bfloat16_as_ushort(b) << 16);
}

// ================= prep_w1 ================================================
__global__ void prep_w1(const float* __restrict__ w)
{
    int idx = blockIdx.x * 256 + threadIdx.x;
    if (idx >= 128 * 2048) return;
    int oc = idx >> 11, ic = idx & 2047;
    const float* src = w + (size_t)oc * 18432 + (size_t)ic * 9;
#pragma unroll
    for (int t = 0; t < 9; t++) {
        __nv_bfloat16 h, l;
        bfsplit(__ldg(&src[t]), h, l);
        size_t d = ((size_t)t * 128 + oc) * 2048 + ic;
        g_wh[d] = h; g_wl[d] = l;
    }
}

// ================= prep_w23 ===============================================
__global__ void prep_w23(const float* __restrict__ w2, const float* __restrict__ w3)
{
    int idx = blockIdx.x * 256 + threadIdx.x;
    if (idx >= 2 * 128 * 128) return;
    int which = idx >> 14, r = idx & 16383;
    int oc = r >> 7, ic = r & 127;
    const float* src = (which ? w3 : w2) + (size_t)(oc * 128 + ic) * 9;
    __nv_bfloat16* dh = which ? g_w3h : g_w2h;
    __nv_bfloat16* dl = which ? g_w3l : g_w2l;
#pragma unroll
    for (int t = 0; t < 9; t++) {
        __nv_bfloat16 h, l;
        bfsplit(__ldg(&src[t]), h, l);
        size_t d = ((size_t)t * 128 + oc) * 128 + ic;
        dh[d] = h; dl[d] = l;
    }
}

// ================= prep_in ================================================
__global__ void prep_in(const float* __restrict__ in)
{
    __shared__ float s_in[32][197];
    const int icb = blockIdx.x;
    const int b   = blockIdx.y;
    const int tid = threadIdx.x;

    const float* src = in + ((size_t)b * 2048 + icb * 32) * 196;
    for (int i = tid; i < 32 * 196; i += 256)
        s_in[i / 196][i % 196] = __ldg(&src[i]);
    __syncthreads();

    for (int i = tid; i < 288 * 16; i += 256) {
        int pos = i >> 4, icp = i & 15;
        int py = pos / 18, px = pos % 18;
        int iy = py - 1, ix = px - 1;
        float v0 = 0.f, v1 = 0.f;
        if ((unsigned)iy < 14u && (unsigned)ix < 14u) {
            v0 = s_in[icp * 2][iy * 14 + ix];
            v1 = s_in[icp * 2 + 1][iy * 14 + ix];
        }
        __nv_bfloat16 h0, l0, h1, l1;
        bfsplit(v0, h0, l0); bfsplit(v1, h1, l1);
        size_t d = ((size_t)b * 288 + pos) * 2048 + icb * 32 + icp * 2;
        *(uint32_t*)&g_ih[d] = pkbf(h0, h1);
        *(uint32_t*)&g_il[d] = pkbf(l0, l1);
    }
}

// ================= conv1 via mma.sync =====================================
#define SA_H   0
#define SA_L   18432
#define SB_H   36864
#define SB_L   69120
#define STG_SZ 101376
#define SM_TOT (2 * STG_SZ)

__global__ void __launch_bounds__(256) conv1_mma()
{
    extern __shared__ __align__(16) char smem[];
    const uint32_t sb = smem_to_u32(smem);
    const int tid = threadIdx.x, wid = tid >> 5, lane = tid & 31;
    const int t = blockIdx.x, b = blockIdx.y;
    const int dy = t / 3 - 1, dx = t % 3 - 1;

    const int mrow = wid & 3;
    const int ncol = wid >> 2;

    float acc[2][14][4];
#pragma unroll
    for (int mt = 0; mt < 2; mt++)
#pragma unroll
        for (int nt = 0; nt < 14; nt++)
#pragma unroll
            for (int i = 0; i < 4; i++) acc[mt][nt][i] = 0.f;

    const __nv_bfloat16* ah0 = g_wh + ((size_t)t * 128) * 2048;
    const __nv_bfloat16* al0 = g_wl + ((size_t)t * 128) * 2048;
    const __nv_bfloat16* bh0 = g_ih + (size_t)b * 288 * 2048;
    const __nv_bfloat16* bl0 = g_il + (size_t)b * 288 * 2048;

    auto fill = [&](int stage, int c) {
        const uint32_t s0 = sb + stage * STG_SZ;
        const int kof = c * 64;
        for (int idx = tid; idx < 1024; idx += 256) {
            int row = idx >> 3, seg = idx & 7;
            uint32_t off = (uint32_t)(row * 144 + seg * 16);
            size_t so = (size_t)row * 2048 + kof + seg * 8;
            cpa16(s0 + SA_H + off, ah0 + so);
            cpa16(s0 + SA_L + off, al0 + so);
        }
        for (int idx = tid; idx < 1792; idx += 256) {
            int row = idx >> 3, seg = idx & 7;
            int y = row >> 4, x = row & 15;
            int pos = (y + dy + 1) * 18 + (x + dx + 1);
            uint32_t off = (uint32_t)(row * 144 + seg * 16);
            size_t so = (size_t)pos * 2048 + kof + seg * 8;
            cpa16(s0 + SB_H + off, bh0 + so);
            cpa16(s0 + SB_L + off, bl0 + so);
        }
        asm volatile("cp.async.commit_group;" ::: "memory");
    };

    const uint32_t aRow = (uint32_t)(lane & 15);
    const uint32_t aHalf = (uint32_t)(lane >> 4) * 16;
    const uint32_t bRow = (uint32_t)(lane & 7);
    const uint32_t bHalf = (uint32_t)((lane >> 3) & 1) * 16;

    fill(0, 0);
    int s = 0;
    for (int c = 0; c < NCHUNK; c++) {
        if (c + 1 < NCHUNK) {
            fill(s ^ 1, c + 1);
            asm volatile("cp.async.wait_group 1;" ::: "memory");
        } else {
            asm volatile("cp.async.wait_group 0;" ::: "memory");
        }
        __syncthreads();

        const uint32_t s0 = sb + s * STG_SZ;
#pragma unroll
        for (int kkstep = 0; kkstep < 4; kkstep++) {
            const uint32_t kb = (uint32_t)kkstep * 32;
            uint32_t ah[2][4], al[2][4];
#pragma unroll
            for (int mt = 0; mt < 2; mt++) {
                uint32_t ra = (uint32_t)((mrow * 32 + mt * 16 + aRow) * 144) + kb + aHalf;
                ldsm_x4(ah[mt][0], ah[mt][1], ah[mt][2], ah[mt][3], s0 + SA_H + ra);
                ldsm_x4(al[mt][0], al[mt][1], al[mt][2], al[mt][3], s0 + SA_L + ra);
            }
            // nt-pair processing: 4 independent accumulators in flight (ILP 4).
            // Per-acc MMA order stays h*bh, h*bl, l*bh -> bit-identical results.
#pragma unroll
            for (int ntp = 0; ntp < 7; ntp++) {
                uint32_t bh[2][2], bl[2][2];
#pragma unroll
                for (int j = 0; j < 2; j++) {
                    uint32_t rb = (uint32_t)((ncol * 112 + (2 * ntp + j) * 8 + bRow) * 144) + kb + bHalf;
                    ldsm_x2(bh[j][0], bh[j][1], s0 + SB_H + rb);
                    ldsm_x2(bl[j][0], bl[j][1], s0 + SB_L + rb);
                }
#pragma unroll
                for (int mt = 0; mt < 2; mt++)
#pragma unroll
                    for (int j = 0; j < 2; j++)
                        mma16816(acc[mt][2 * ntp + j], ah[mt][0], ah[mt][1], ah[mt][2], ah[mt][3],
                                 bh[j][0], bh[j][1]);
#pragma unroll
                for (int mt = 0; mt < 2; mt++)
#pragma unroll
                    for (int j = 0; j < 2; j++)
                        mma16816(acc[mt][2 * ntp + j], ah[mt][0], ah[mt][1], ah[mt][2], ah[mt][3],
                                 bl[j][0], bl[j][1]);
#pragma unroll
                for (int mt = 0; mt < 2; mt++)
#pragma unroll
                    for (int j = 0; j < 2; j++)
                        mma16816(acc[mt][2 * ntp + j], al[mt][0], al[mt][1], al[mt][2], al[mt][3],
                                 bh[j][0], bh[j][1]);
            }
        }
        __syncthreads();
        s ^= 1;
    }

    const int r = lane >> 2, q = lane & 3;
    float* pp = g_part1 + (size_t)t * NP1 + ((size_t)b * 128) * 196;
#pragma unroll
    for (int mt = 0; mt < 2; mt++) {
        int oc0 = mrow * 32 + mt * 16 + r;
#pragma unroll
        for (int nt = 0; nt < 14; nt++) {
            int n0 = ncol * 112 + nt * 8 + 2 * q;
            int y0 = n0 >> 4, x0 = n0 & 15;
            int y1 = (n0 + 1) >> 4, x1 = (n0 + 1) & 15;
            if (x0 < 14) {
                pp[(size_t)oc0 * 196 + y0 * 14 + x0]       = acc[mt][nt][0];
                pp[(size_t)(oc0 + 8) * 196 + y0 * 14 + x0] = acc[mt][nt][2];
            }
            if (x1 < 14) {
                pp[(size_t)oc0 * 196 + y1 * 14 + x1]       = acc[mt][nt][1];
                pp[(size_t)(oc0 + 8) * 196 + y1 * 14 + x1] = acc[mt][nt][3];
            }
        }
    }
}

// ====== finalize1: split-K reduce + bias + relu + write d1 planes =========
__global__ void finalize1_kernel(const float* __restrict__ bias)
{
    int n = blockIdx.x * 256 + threadIdx.x;
    if (n >= NP1) return;
    float s = 0.f;
#pragma unroll
    for (int k = 0; k < KSPLIT; k++) s += g_part1[(size_t)k * NP1 + n];
    int p = n % 196;
    int oc = (n / 196) & 127;
    int b = n / (196 * 128);
    float v = fmaxf(s + __ldg(&bias[oc]), 0.f);
    g_d1[n] = v;
    // bf16 hi/lo plane for conv2's MMA B operand (borders stay zero-init)
    int pos = (p / 14 + 1) * 16 + (p % 14 + 1);
    __nv_bfloat16 h, l;
    bfsplit(v, h, l);
    size_t d = ((size_t)b * 256 + pos) * 128 + oc;
    g_d1h[d] = h;
    g_d1l[d] = l;
}

// ================= conv23_mma =============================================
#define C23_A_H  0
#define C23_A_L  34816
#define C23_B_H  69632
#define C23_B_L  87040
#define C23_TOT  104448

__global__ void __launch_bounds__(256) conv23_mma(const __nv_bfloat16* __restrict__ wh,
                                                  const __nv_bfloat16* __restrict__ wl,
                                                  const __nv_bfloat16* __restrict__ inh,
                                                  const __nv_bfloat16* __restrict__ inl,
                                                  float* __restrict__ part,
                                                  int OW, int NVALID)
{
    extern __shared__ __align__(16) char smem[];
    const uint32_t sb = smem_to_u32(smem);
    const int tid = threadIdx.x, wid = tid >> 5, lane = tid & 31;
    const int t = blockIdx.x, b = blockIdx.y;
    const int dy = t / 3 - 1, dx = t % 3 - 1;
    const int mrow = wid & 3;
    const int ncol = wid >> 2;

    const __nv_bfloat16* ah0 = wh + (size_t)t * 128 * 128;
    const __nv_bfloat16* al0 = wl + (size_t)t * 128 * 128;
    const __nv_bfloat16* bh0 = inh + (size_t)b * 256 * 128;
    const __nv_bfloat16* bl0 = inl + (size_t)b * 256 * 128;

    for (int idx = tid; idx < 2048; idx += 256) {
        int row = idx >> 4, seg = idx & 15;
        uint32_t off = (uint32_t)(row * 272 + seg * 16);
        size_t so = (size_t)row * 128 + seg * 8;
        cpa16(sb + C23_A_H + off, ah0 + so);
        cpa16(sb + C23_A_L + off, al0 + so);
    }
    for (int idx = tid; idx < 1024; idx += 256) {
        int row = idx >> 4, seg = idx & 15;
        int pos = 0;
        if (row < NVALID) {
            int oy = row / OW, ox = row % OW;
            pos = (2 * oy + dy + 1) * 16 + (2 * ox + dx + 1);
        }
        uint32_t off = (uint32_t)(row * 272 + seg * 16);
        size_t so = (size_t)pos * 128 + seg * 8;
        cpa16(sb + C23_B_H + off, bh0 + so);
        cpa16(sb + C23_B_L + off, bl0 + so);
    }
    asm volatile("cp.async.commit_group;" ::: "memory");
    asm volatile("cp.async.wait_group 0;" ::: "memory");
    __syncthreads();

    float acc[2][4][4];
#pragma unroll
    for (int mt = 0; mt < 2; mt++)
#pragma unroll
        for (int nt = 0; nt < 4; nt++)
#pragma unroll
            for (int i = 0; i < 4; i++) acc[mt][nt][i] = 0.f;

    const uint32_t aRow = (uint32_t)(lane & 15);
    const uint32_t aHalf = (uint32_t)(lane >> 4) * 16;
    const uint32_t bRow = (uint32_t)(lane & 7);
    const uint32_t bHalf = (uint32_t)((lane >> 3) & 1) * 16;

#pragma unroll
    for (int kkstep = 0; kkstep < 8; kkstep++) {
        const uint32_t kb = (uint32_t)kkstep * 32;
        uint32_t ah[2][4], al[2][4];
#pragma unroll
        for (int mt = 0; mt < 2; mt++) {
            uint32_t ra = (uint32_t)((mrow * 32 + mt * 16 + aRow) * 272) + kb + aHalf;
            ldsm_x4(ah[mt][0], ah[mt][1], ah[mt][2], ah[mt][3], sb + C23_A_H + ra);
            ldsm_x4(al[mt][0], al[mt][1], al[mt][2], al[mt][3], sb + C23_A_L + ra);
        }
#pragma unroll
        for (int ntp = 0; ntp < 2; ntp++) {
            uint32_t bh[2][2], bl[2][2];
#pragma unroll
            for (int j = 0; j < 2; j++) {
                uint32_t rb = (uint32_t)((ncol * 32 + (2 * ntp + j) * 8 + bRow) * 272) + kb + bHalf;
                ldsm_x2(bh[j][0], bh[j][1], sb + C23_B_H + rb);
                ldsm_x2(bl[j][0], bl[j][1], sb + C23_B_L + rb);
            }
#pragma unroll
            for (int mt = 0; mt < 2; mt++)
#pragma unroll
                for (int j = 0; j < 2; j++)
                    mma16816(acc[mt][2 * ntp + j], ah[mt][0], ah[mt][1], ah[mt][2], ah[mt][3],
                             bh[j][0], bh[j][1]);
#pragma unroll
            for (int mt = 0; mt < 2; mt++)
#pragma unroll
                for (int j = 0; j < 2; j++)
                    mma16816(acc[mt][2 * ntp + j], ah[mt][0], ah[mt][1], ah[mt][2], ah[mt][3],
                             bl[j][0], bl[j][1]);
#pragma unroll
            for (int mt = 0; mt < 2; mt++)
#pragma unroll
                for (int j = 0; j < 2; j++)
                    mma16816(acc[mt][2 * ntp + j], al[mt][0], al[mt][1], al[mt][2], al[mt][3],
                             bh[j][0], bh[j][1]);
        }
    }

    const int r = lane >> 2, q = lane & 3;
    float* pp = part + ((size_t)t * BATCH + b) * 128 * NVALID;
#pragma unroll
    for (int mt = 0; mt < 2; mt++) {
        int oc0 = mrow * 32 + mt * 16 + r;
#pragma unroll
        for (int nt = 0; nt < 4; nt++) {
            int n0 = ncol * 32 + nt * 8 + 2 * q;
            if (n0 < NVALID) {
                pp[(size_t)oc0 * NVALID + n0]       = acc[mt][nt][0];
                pp[(size_t)(oc0 + 8) * NVALID + n0] = acc[mt][nt][2];
            }
            if (n0 + 1 < NVALID) {
                pp[(size_t)oc0 * NVALID + n0 + 1]       = acc[mt][nt][1];
                pp[(size_t)(oc0 + 8) * NVALID + n0 + 1] = acc[mt][nt][3];
            }
        }
    }
}

// ====== reduce2: 9-way reduce + bias + relu + write d2 planes =============
__global__ void reduce2_kernel(const float* __restrict__ bias)
{
    int n = blockIdx.x * 256 + threadIdx.x;
    if (n >= N2) return;
    float s = __ldg(&bias[(n / 49) & 127]);
#pragma unroll
    for (int k = 0; k < 9; k++) s += g_p2[(size_t)k * N2 + n];
    float v = fmaxf(s, 0.f);
    g_d2[n] = v;
    int p = n % 49;
    int oc = (n / 49) & 127;
    int b = n / (49 * 128);
    int pos = (p / 7 + 1) * 16 + (p % 7 + 1);
    __nv_bfloat16 h, l;
    bfsplit(v, h, l);
    size_t d = ((size_t)b * 256 + pos) * 128 + oc;
    g_d2h[d] = h;
    g_d2l[d] = l;
}

__global__ void reduce3_kernel(const float* __restrict__ bias)
{
    int n = blockIdx.x * 256 + threadIdx.x;
    if (n >= N3) return;
    float s = __ldg(&bias[(n / 16) & 127]);
#pragma unroll
    for (int k = 0; k < 9; k++) s += g_p3[(size_t)k * N3 + n];
    g_d3[n] = fmaxf(s, 0.f);
}

// ================= tidy 1x1 convs -> concatenated scores =================
__global__ void tidy_kernel(const float* __restrict__ wt1, const float* __restrict__ bt1,
                            const float* __restrict__ wt2, const float* __restrict__ bt2,
                            const float* __restrict__ wt3, const float* __restrict__ bt3,
                            float* __restrict__ out)
{
    int n = blockIdx.x * 256 + threadIdx.x;
    if (n >= BATCH * NA) return;
    int b = n / NA, j = n % NA;
    const float* src; const float* wt; float bias; int c, p, stride;
    if (j < 1176) {
        c = j / 196; p = j % 196;
        src = g_d1 + (size_t)b * 128 * 196; stride = 196;
        wt = wt1; bias = __ldg(&bt1[c]);
    } else if (j < 1470) {
        int jj = j - 1176; c = jj / 49; p = jj % 49;
        src = g_d2 + (size_t)b * 128 * 49; stride = 49;
        wt = wt2; bias = __ldg(&bt2[c]);
    } else {
        int jj = j - 1470; c = jj / 16; p = jj % 16;
        src = g_d3 + (size_t)b * 128 * 16; stride = 16;
        wt = wt3; bias = __ldg(&bt3[c]);
    }
    const float4* wv = (const float4*)(wt + (size_t)c * 128);
    float a0 = 0.f, a1 = 0.f, a2 = 0.f, a3 = 0.f;
#pragma unroll 8
    for (int i = 0; i < 32; i++) {
        float4 w4 = __ldg(&wv[i]);
        int ic = 4 * i;
        a0 = fmaf(src[(size_t)(ic + 0) * stride + p], w4.x, a0);
        a1 = fmaf(src[(size_t)(ic + 1) * stride + p], w4.y, a1);
        a2 = fmaf(src[(size_t)(ic + 2) * stride + p], w4.z, a2);
        a3 = fmaf(src[(size_t)(ic + 3) * stride + p], w4.w, a3);
    }
    float acc = bias + ((a0 + a1) + (a2 + a3));
    g_score[n] = acc;
    out[OFF_SCORE + n] = acc;
}

// ================= greedy NMS ==============================================
__global__ void nms_kernel(const int* __restrict__ anchors, float* __restrict__ out)
{
    int b = blockIdx.x, tid = threadIdx.x;
    __shared__ float s[NA];
    __shared__ float rv[256];
    __shared__ int   ri[256];
    __shared__ float pbox[4];
    __shared__ float parea;

    for (int j = tid; j < NA; j += 256) s[j] = g_score[b * NA + j];
    __syncthreads();

    for (int k = 0; k < TOPN; k++) {
        float bv = neg_inf(); int bi = 0x7fffffff;
        for (int j = tid; j < NA; j += 256) {
            float v = s[j];
            if (v > bv || (v == bv && j < bi)) { bv = v; bi = j; }
        }
        rv[tid] = bv; ri[tid] = bi;
        __syncthreads();
        for (int st = 128; st > 0; st >>= 1) {
            if (tid < st) {
                float v2 = rv[tid + st]; int i2 = ri[tid + st];
                if (v2 > rv[tid] || (v2 == rv[tid] && i2 < ri[tid])) {
                    rv[tid] = v2; ri[tid] = i2;
                }
            }
            __syncthreads();
        }
        if (tid == 0) {
            int pick = ri[0];
            const int* a = anchors + (size_t)pick * 4;
            pbox[0] = (float)a[0]; pbox[1] = (float)a[1];
            pbox[2] = (float)a[2]; pbox[3] = (float)a[3];
            parea = (pbox[2] - pbox[0]) * (pbox[3] - pbox[1]);
            g_topidx[b * TOPN + k] = pick;
            out[OFF_TIDX  + b * TOPN + k] = (float)pick;
            out[OFF_TPROB + b * TOPN + k] = rv[0];
        }
        __syncthreads();
        float y0 = pbox[0], x0 = pbox[1], y1 = pbox[2], x1 = pbox[3], pa = parea;
        for (int j = tid; j < NA; j += 256) {
            const int* a = anchors + (size_t)j * 4;
            float ay0 = (float)a[0], ax0 = (float)a[1];
            float ay1 = (float)a[2], ax1 = (float)a[3];
            float iy = fmaxf(fminf(ay1, y1) - fmaxf(ay0, y0), 0.f);
            float ix = fmaxf(fminf(ax1, x1) - fmaxf(ax0, x0), 0.f);
            float inter = iy * ix;
            float area  = (ay1 - ay0) * (ax1 - ax0);
            float iou = inter / (area + pa - inter);
            if (iou >= 0.25f) s[j] = neg_inf();
        }
        __syncthreads();
    }
}

// ================= crop + bilinear resize =================================
__device__ __forceinline__ float fetchpix(const float* __restrict__ xb, int yy, int xx)
{
    yy -= PAD_S; xx -= PAD_S;
    if ((unsigned)yy < (unsigned)IM_S && (unsigned)xx < (unsigned)IM_S)
        return __ldg(&xb[(size_t)yy * IM_S + xx]);
    return 0.f;
}

__global__ void crop_kernel(const float* __restrict__ x,
                            const int* __restrict__ anchors,
                            float* __restrict__ out)
{
    const int crop = blockIdx.x;
    const int oy   = blockIdx.y;
    const int ox   = threadIdx.x;
    const int b    = crop >> 2;

    const int pick = g_topidx[crop];
    const int* a = anchors + (size_t)pick * 4;
    float y0 = (float)a[0], x0 = (float)a[1], y1 = (float)a[2], x1 = (float)a[3];

    float ty = (float)oy / 223.0f;
    float tx = (float)ox / 223.0f;
    float ys = y0 + ty * (y1 - y0 - 1.0f);
    float xs = x0 + tx * (x1 - x0 - 1.0f);
    int yi0 = (int)floorf(ys); int yi1 = min(yi0 + 1, HP_S - 1);
    int xi0 = (int)floorf(xs); int xi1 = min(xi0 + 1, HP_S - 1);
    float wy = ys - (float)yi0;
    float wx = xs - (float)xi0;
    float c00 = (1.f - wy) * (1.f - wx);
    float c01 = (1.f - wy) * wx;
    float c10 = wy * (1.f - wx);
    float c11 = wy * wx;

#pragma unroll
    for (int c = 0; c < 3; c++) {
        const float* xb = x + ((size_t)b * 3 + c) * IM_S * IM_S;
        float v = fetchpix(xb, yi0, xi0) * c00
                + fetchpix(xb, yi0, xi1) * c01
                + fetchpix(xb, yi1, xi0) * c10
                + fetchpix(xb, yi1, xi1) * c11;
        out[(((size_t)crop * 3 + c) * OUT_S + oy) * OUT_S + ox] = v;
    }
}

// =========================================================================
extern "C" void kernel_launch(void* const* d_in, const int* in_sizes, int n_in,
                              void* d_out, int out_size)
{
    const float* x    = (const float*)d_in[0];
    const float* rpn  = (const float*)d_in[1];
    const float* w1   = (const float*)d_in[2];
    const float* b1   = (const float*)d_in[3];
    const float* w2   = (const float*)d_in[4];
    const float* b2   = (const float*)d_in[5];
    const float* w3   = (const float*)d_in[6];
    const float* b3   = (const float*)d_in[7];
    const float* wt1  = (const float*)d_in[8];
    const float* bt1  = (const float*)d_in[9];
    const float* wt2  = (const float*)d_in[10];
    const float* bt2  = (const float*)d_in[11];
    const float* wt3  = (const float*)d_in[12];
    const float* bt3  = (const float*)d_in[13];
    const int*   anc  = (const int*)d_in[14];
    float* out = (float*)d_out;

    cudaFuncSetAttribute(conv1_mma, cudaFuncAttributeMaxDynamicSharedMemorySize, SM_TOT);
    cudaFuncSetAttribute(conv23_mma, cudaFuncAttributeMaxDynamicSharedMemorySize, C23_TOT);

    float *p2, *p3;
    cudaGetSymbolAddress((void**)&p2, g_p2);
    cudaGetSymbolAddress((void**)&p3, g_p3);
    __nv_bfloat16 *w2h, *w2l, *w3h, *w3l, *d1h, *d1l, *d2h, *d2l;
    cudaGetSymbolAddress((void**)&w2h, g_w2h);
    cudaGetSymbolAddress((void**)&w2l, g_w2l);
    cudaGetSymbolAddress((void**)&w3h, g_w3h);
    cudaGetSymbolAddress((void**)&w3l, g_w3l);
    cudaGetSymbolAddress((void**)&d1h, g_d1h);
    cudaGetSymbolAddress((void**)&d1l, g_d1l);
    cudaGetSymbolAddress((void**)&d2h, g_d2h);
    cudaGetSymbolAddress((void**)&d2l, g_d2l);

    prep_w1<<<(128 * 2048 + 255) / 256, 256>>>(w1);
    prep_w23<<<(2 * 128 * 128 + 255) / 256, 256>>>(w2, w3);
    prep_in<<<dim3(64, BATCH), 256>>>(rpn);

    conv1_mma<<<dim3(KSPLIT, BATCH), 256, SM_TOT>>>();   // launch #4: ncu slot
    finalize1_kernel<<<(NP1 + 255) / 256, 256>>>(b1);    // fused: d1 + d1 planes

    conv23_mma<<<dim3(9, BATCH), 256, C23_TOT>>>(w2h, w2l, d1h, d1l, p2, 7, 49);
    reduce2_kernel<<<(N2 + 255) / 256, 256>>>(b2);       // fused: d2 + d2 planes

    conv23_mma<<<dim3(9, BATCH), 256, C23_TOT>>>(w3h, w3l, d2h, d2l, p3, 4, 16);
    reduce3_kernel<<<(N3 + 255) / 256, 256>>>(b3);

    tidy_kernel<<<(BATCH * NA + 255) / 256, 256>>>(wt1, bt1, wt2, bt2, wt3, bt3, out);
    nms_kernel<<<BATCH, 256>>>(anc, out);
    crop_kernel<<<dim3(BATCH * TOPN, OUT_S), OUT_S>>>(x, anc, out);
}